// round 2
// baseline (speedup 1.0000x reference)
#include <cuda_runtime.h>
#include <math.h>

// Problem dims
#define Bdim 128
#define Tdim 64
#define NAa  10
#define NVv  16
#define Kk   4
#define SDd  512
#define Hh   256
#define Ee   32
#define ROWS (Bdim * Tdim)        // 8192
#define NCAT 844                  // 256 + 256 + 256 + 10 + 1 + 1 + 32 + 32
#define N2   ((NVv + 1) * Ee)     // 544

// Scratch (static __device__ allocations -- no cudaMalloc allowed)
__device__ float g_H1[(size_t)ROWS * NCAT];     // ~27.6 MB
__device__ float g_W1F[(size_t)ROWS * N2];      // ~17.8 MB
__device__ float g_Bcat[(size_t)SDd * NCAT];    // ~1.7 MB
__device__ float g_biascat[NCAT];
__device__ float g_hdelta[Hh];
__device__ float g_gdelta[1];

// ---------------------------------------------------------------------------
// Pack kernel: build concatenated weight matrix Bcat (512 x 844) + bias vector
// Column map:
//  [0,256)   w00_l1_W rows 0..511        bias: w00_l1_b
//  [256,512) w1_l1_W                     bias: w1_l1_b
//  [512,768) w2_l1_W                     bias: w2_l1_b
//  [768,778) w01_W                       bias: w01_b
//  778       b01_W                       bias: b01_b
//  779       b00_W rows 0..511           bias: b00_b
//  [780,812) b1_W                        bias: b1_b
//  [812,844) b2_l1_W                     bias: b2_l1_b
// ---------------------------------------------------------------------------
__global__ void pack_kernel(
    const float* __restrict__ w00_l1_W, const float* __restrict__ w00_l1_b,
    const float* __restrict__ w1_l1_W,  const float* __restrict__ w1_l1_b,
    const float* __restrict__ w2_l1_W,  const float* __restrict__ w2_l1_b,
    const float* __restrict__ w01_W,    const float* __restrict__ w01_b,
    const float* __restrict__ b01_W,    const float* __restrict__ b01_b,
    const float* __restrict__ b00_W,    const float* __restrict__ b00_b,
    const float* __restrict__ b1_W,     const float* __restrict__ b1_b,
    const float* __restrict__ b2_l1_W,  const float* __restrict__ b2_l1_b)
{
    int idx = blockIdx.x * blockDim.x + threadIdx.x;
    int total = SDd * NCAT;
    if (idx < total) {
        int k = idx / NCAT;
        int c = idx - k * NCAT;
        float v;
        if      (c < 256) v = w00_l1_W[k * 256 + c];
        else if (c < 512) v = w1_l1_W[k * 256 + (c - 256)];
        else if (c < 768) v = w2_l1_W[k * 256 + (c - 512)];
        else if (c < 778) v = w01_W[k * 10 + (c - 768)];
        else if (c == 778) v = b01_W[k];
        else if (c == 779) v = b00_W[k];
        else if (c < 812) v = b1_W[k * 32 + (c - 780)];
        else              v = b2_l1_W[k * 32 + (c - 812)];
        g_Bcat[idx] = v;
    }
    if (idx < NCAT) {
        int c = idx;
        float v;
        if      (c < 256) v = w00_l1_b[c];
        else if (c < 512) v = w1_l1_b[c - 256];
        else if (c < 768) v = w2_l1_b[c - 512];
        else if (c < 778) v = w01_b[c - 768];
        else if (c == 778) v = b01_b[0];
        else if (c == 779) v = b00_b[0];
        else if (c < 812) v = b1_b[c - 780];
        else              v = b2_l1_b[c - 812];
        g_biascat[c] = v;
    }
}

// deltas from the "all-ones onehot row" quirk: contributions of rows [512,528)
__global__ void delta_kernel(const float* __restrict__ w00_l1_W,
                             const float* __restrict__ b00_W)
{
    int t = threadIdx.x;
    if (t < Hh) {
        float s = 0.f;
        #pragma unroll
        for (int j = 0; j < NVv; j++) s += w00_l1_W[(SDd + j) * 256 + t];
        g_hdelta[t] = s;
    }
    if (t == 0) {
        float s = 0.f;
        #pragma unroll
        for (int j = 0; j < NVv; j++) s += b00_W[SDd + j];
        g_gdelta[0] = s;
    }
}

// ---------------------------------------------------------------------------
// Tiled fp32 GEMM: C[M x N] = op(A)[M x K] @ B[K x N] + bias[N]
// BM=128, BN=64, BK=16, 256 threads, 8x4 micro-tile per thread.
// M is exactly grid.y * 128; K is a multiple of 16; N handled with bounds.
// ---------------------------------------------------------------------------
template <bool RELU_A>
__global__ void __launch_bounds__(256)
gemm_kernel(const float* __restrict__ A, int lda,
            const float* __restrict__ B, int ldb,
            const float* __restrict__ bias,
            float* __restrict__ C, int ldc,
            int N, int K)
{
    __shared__ float As[16][128];   // transposed A tile: As[k][m]
    __shared__ float Bs[16][68];    // padded

    const int tid = threadIdx.x;
    const int tx = tid & 15;        // N direction (x4)
    const int ty = tid >> 4;        // M direction (x8)
    const int bm = blockIdx.y * 128;
    const int bn = blockIdx.x * 64;

    float acc[8][4];
    #pragma unroll
    for (int m = 0; m < 8; m++)
        #pragma unroll
        for (int n = 0; n < 4; n++) acc[m][n] = 0.f;

    const bool nfull = (bn + 64 <= N);
    const int arow0 = tid >> 2;
    const int acol  = (tid & 3) << 2;
    const int brow  = tid >> 4;
    const int bcol  = (tid & 15) << 2;

    for (int k0 = 0; k0 < K; k0 += 16) {
        // A tile: 128x16, each thread 2 float4 loads, store transposed
        #pragma unroll
        for (int i = 0; i < 2; i++) {
            int arow = arow0 + i * 64;
            float4 v = *(const float4*)(A + (size_t)(bm + arow) * lda + k0 + acol);
            if (RELU_A) {
                v.x = fmaxf(v.x, 0.f); v.y = fmaxf(v.y, 0.f);
                v.z = fmaxf(v.z, 0.f); v.w = fmaxf(v.w, 0.f);
            }
            As[acol + 0][arow] = v.x;
            As[acol + 1][arow] = v.y;
            As[acol + 2][arow] = v.z;
            As[acol + 3][arow] = v.w;
        }
        // B tile: 16x64, each thread one float4 (or guarded scalars on edge)
        if (nfull) {
            float4 v = *(const float4*)(B + (size_t)(k0 + brow) * ldb + bn + bcol);
            Bs[brow][bcol + 0] = v.x;
            Bs[brow][bcol + 1] = v.y;
            Bs[brow][bcol + 2] = v.z;
            Bs[brow][bcol + 3] = v.w;
        } else {
            #pragma unroll
            for (int j = 0; j < 4; j++) {
                int c = bn + bcol + j;
                Bs[brow][bcol + j] = (c < N) ? B[(size_t)(k0 + brow) * ldb + c] : 0.f;
            }
        }
        __syncthreads();

        #pragma unroll
        for (int kk = 0; kk < 16; kk++) {
            float ra[8], rb[4];
            #pragma unroll
            for (int m = 0; m < 8; m++) ra[m] = As[kk][ty * 8 + m];
            #pragma unroll
            for (int n = 0; n < 4; n++) rb[n] = Bs[kk][tx * 4 + n];
            #pragma unroll
            for (int m = 0; m < 8; m++)
                #pragma unroll
                for (int n = 0; n < 4; n++) acc[m][n] += ra[m] * rb[n];
        }
        __syncthreads();
    }

    #pragma unroll
    for (int m = 0; m < 8; m++) {
        int rrow = bm + ty * 8 + m;
        #pragma unroll
        for (int n = 0; n < 4; n++) {
            int c = bn + tx * 4 + n;
            if (c < N) C[(size_t)rrow * ldc + c] = acc[m][n] + bias[c];
        }
    }
}

// ---------------------------------------------------------------------------
// Final fused kernel: one warp per row (b,t).
// ---------------------------------------------------------------------------
__global__ void __launch_bounds__(256)
final_kernel(const float* __restrict__ qvals,
             const int*   __restrict__ cr,
             const float* __restrict__ w00_l2_W,  // (256,4)
             const float* __restrict__ w00_l2_b,  // (4)
             const float* __restrict__ w2_l2_W,   // (256,32)
             const float* __restrict__ w2_l2_b,   // (32)
             const float* __restrict__ b2_l2_W,   // (32,1)
             const float* __restrict__ b2_l2_b,   // (1)
             float* __restrict__ out)
{
    __shared__ float s_h[8][Hh];
    __shared__ float s_a2[8][Hh];
    __shared__ float s_q[8][NAa];

    const int w = threadIdx.x >> 5;
    const int l = threadIdx.x & 31;
    const int r = blockIdx.x * 8 + w;
    const int b = r >> 6;                 // batch index (T = 64)
    const float* __restrict__ row = g_H1 + (size_t)r * NCAT;

    for (int i = l; i < Hh; i += 32) {
        s_h[w][i]  = row[i];
        s_a2[w][i] = fmaxf(row[512 + i], 0.f);
    }
    if (l < NAa) s_q[w][l] = qvals[r * NAa + l];
    __syncwarp();

    const bool mod = (b < NVv);

    // --- w00_l2: common + modified (only meaningful when mod) ---
    float acc0[4] = {0.f, 0.f, 0.f, 0.f};
    float accm[4] = {0.f, 0.f, 0.f, 0.f};
    for (int kk = l; kk < Hh; kk += 32) {
        float hb = s_h[w][kk];
        float h  = fmaxf(hb, 0.f);
        float hm = fmaxf(hb + g_hdelta[kk], 0.f);
        float4 wv = *(const float4*)(w00_l2_W + kk * 4);
        acc0[0] += h  * wv.x; acc0[1] += h  * wv.y; acc0[2] += h  * wv.z; acc0[3] += h  * wv.w;
        accm[0] += hm * wv.x; accm[1] += hm * wv.y; accm[2] += hm * wv.z; accm[3] += hm * wv.w;
    }
    #pragma unroll
    for (int o = 0; o < 4; o++) {
        #pragma unroll
        for (int off = 16; off; off >>= 1) {
            acc0[o] += __shfl_xor_sync(0xffffffffu, acc0[o], off);
            accm[o] += __shfl_xor_sync(0xffffffffu, accm[o], off);
        }
    }
    float w0c[4], w0m[4];
    #pragma unroll
    for (int o = 0; o < 4; o++) {
        w0c[o] = fabsf(acc0[o] + w00_l2_b[o]);
        w0m[o] = fabsf(accm[o] + w00_l2_b[o]);
    }

    // --- w2 = |relu(a2) @ w2_l2_W + b|, lane l = output channel ---
    float acc2 = 0.f;
    #pragma unroll 8
    for (int kk = 0; kk < Hh; kk++) acc2 += s_a2[w][kk] * w2_l2_W[kk * Ee + l];
    float w2a = fabsf(acc2 + w2_l2_b[l]);

    // --- b2 = relu(states@b2_l1 + b) @ b2_l2_W + b2_l2_b ---
    float xb2 = fmaxf(row[812 + l], 0.f) * b2_l2_W[l];
    #pragma unroll
    for (int off = 16; off; off >>= 1) xb2 += __shfl_xor_sync(0xffffffffu, xb2, off);
    float b2 = xb2 + b2_l2_b[0];

    // --- b1 (lane = emb channel) ---
    float b1v = row[780 + l];

    // --- group q-values (lanes 0..15 = variables) and residual mix (lane >=16) ---
    float gq_l;
    if (l < NVv) {
        const int* __restrict__ crr = cr + (size_t)r * (Kk * NVv);
        float g = 0.f;
        #pragma unroll
        for (int k = 0; k < Kk; k++) {
            int idx = crr[k * NVv + l];
            float wk = (mod && l == b) ? w0m[k] : w0c[k];
            g += s_q[w][idx] * wk;
        }
        g += row[779];
        if (mod && l == b) g += g_gdelta[0];
        gq_l = g;
    } else {
        float oth = row[778];
        #pragma unroll
        for (int a = 0; a < NAa; a++) oth += s_q[w][a] * row[768 + a];
        gq_l = oth;
    }

    // --- hidden = elu(gq @ |w1| + b1), lane = emb channel ---
    const float* __restrict__ w1r = g_W1F + (size_t)r * N2;
    float accH = b1v;
    #pragma unroll
    for (int v = 0; v <= NVv; v++) {
        float gqv = __shfl_sync(0xffffffffu, gq_l, v);
        accH += gqv * fabsf(w1r[v * Ee + l]);
    }
    float hidden = (accH > 0.f) ? accH : expm1f(accH);

    float part = hidden * w2a;
    #pragma unroll
    for (int off = 16; off; off >>= 1) part += __shfl_xor_sync(0xffffffffu, part, off);
    if (l == 0) out[r] = part + b2;
}

// ---------------------------------------------------------------------------
extern "C" void kernel_launch(void* const* d_in, const int* in_sizes, int n_in,
                              void* d_out, int out_size)
{
    const float* qvals    = (const float*)d_in[0];
    const int*   cr       = (const int*)  d_in[1];
    const float* states   = (const float*)d_in[2];
    const float* w00_l1_W = (const float*)d_in[3];
    const float* w00_l1_b = (const float*)d_in[4];
    const float* w00_l2_W = (const float*)d_in[5];
    const float* w00_l2_b = (const float*)d_in[6];
    const float* b00_W    = (const float*)d_in[7];
    const float* b00_b    = (const float*)d_in[8];
    const float* w01_W    = (const float*)d_in[9];
    const float* w01_b    = (const float*)d_in[10];
    const float* b01_W    = (const float*)d_in[11];
    const float* b01_b    = (const float*)d_in[12];
    const float* w1_l1_W  = (const float*)d_in[13];
    const float* w1_l1_b  = (const float*)d_in[14];
    const float* w1_l2_W  = (const float*)d_in[15];
    const float* w1_l2_b  = (const float*)d_in[16];
    const float* b1_W     = (const float*)d_in[17];
    const float* b1_b     = (const float*)d_in[18];
    const float* w2_l1_W  = (const float*)d_in[19];
    const float* w2_l1_b  = (const float*)d_in[20];
    const float* w2_l2_W  = (const float*)d_in[21];
    const float* w2_l2_b  = (const float*)d_in[22];
    const float* b2_l1_W  = (const float*)d_in[23];
    const float* b2_l1_b  = (const float*)d_in[24];
    const float* b2_l2_W  = (const float*)d_in[25];
    const float* b2_l2_b  = (const float*)d_in[26];
    float* out = (float*)d_out;

    float *H1, *W1F, *Bcat, *biascat;
    cudaGetSymbolAddress((void**)&H1,      g_H1);
    cudaGetSymbolAddress((void**)&W1F,     g_W1F);
    cudaGetSymbolAddress((void**)&Bcat,    g_Bcat);
    cudaGetSymbolAddress((void**)&biascat, g_biascat);

    // 1) pack weights + biases, compute onehot deltas
    pack_kernel<<<(SDd * NCAT + 255) / 256, 256>>>(
        w00_l1_W, w00_l1_b, w1_l1_W, w1_l1_b, w2_l1_W, w2_l1_b,
        w01_W, w01_b, b01_W, b01_b, b00_W, b00_b, b1_W, b1_b, b2_l1_W, b2_l1_b);
    delta_kernel<<<1, 256>>>(w00_l1_W, b00_W);

    // 2) GEMM1: H1 = states @ Bcat + biascat     (8192 x 512 x 844)
    {
        dim3 grid((NCAT + 63) / 64, ROWS / 128);
        gemm_kernel<false><<<grid, 256>>>(states, SDd, Bcat, NCAT, biascat,
                                          H1, NCAT, NCAT, SDd);
    }

    // 3) GEMM2: W1F = relu(H1[:,256:512]) @ w1_l2_W + w1_l2_b  (8192 x 256 x 544)
    {
        dim3 grid((N2 + 63) / 64, ROWS / 128);
        gemm_kernel<true><<<grid, 256>>>(H1 + 256, NCAT, w1_l2_W, N2, w1_l2_b,
                                         W1F, N2, N2, Hh);
    }

    // 4) fused epilogue: one warp per row
    final_kernel<<<ROWS / 8, 256>>>(qvals, cr,
                                    w00_l2_W, w00_l2_b,
                                    w2_l2_W, w2_l2_b,
                                    b2_l2_W, b2_l2_b,
                                    out);
}

// round 6
// speedup vs baseline: 1.0364x; 1.0364x over previous
#include <cuda_runtime.h>
#include <math.h>

// Problem dims
#define Bdim 128
#define Tdim 64
#define NAa  10
#define NVv  16
#define Kk   4
#define SDd  512
#define Hh   256
#define Ee   32
#define ROWS (Bdim * Tdim)        // 8192
#define NCAT 844                  // 256 + 256 + 256 + 10 + 1 + 1 + 32 + 32
#define N2   ((NVv + 1) * Ee)     // 544

// Scratch (static __device__ allocations -- no cudaMalloc allowed)
__device__ float g_H1[(size_t)ROWS * NCAT];     // ~27.6 MB
__device__ float g_W1F[(size_t)ROWS * N2];      // ~17.8 MB
__device__ float g_Bcat[(size_t)SDd * NCAT];    // ~1.7 MB
__device__ float g_biascat[NCAT];
__device__ float g_hdelta[Hh];
__device__ float g_gdelta[1];

// ---------------------------------------------------------------------------
// Pack kernel: build concatenated weight matrix Bcat (512 x 844) + bias vector
// ---------------------------------------------------------------------------
__global__ void pack_kernel(
    const float* __restrict__ w00_l1_W, const float* __restrict__ w00_l1_b,
    const float* __restrict__ w1_l1_W,  const float* __restrict__ w1_l1_b,
    const float* __restrict__ w2_l1_W,  const float* __restrict__ w2_l1_b,
    const float* __restrict__ w01_W,    const float* __restrict__ w01_b,
    const float* __restrict__ b01_W,    const float* __restrict__ b01_b,
    const float* __restrict__ b00_W,    const float* __restrict__ b00_b,
    const float* __restrict__ b1_W,     const float* __restrict__ b1_b,
    const float* __restrict__ b2_l1_W,  const float* __restrict__ b2_l1_b)
{
    int idx = blockIdx.x * blockDim.x + threadIdx.x;
    int total = SDd * NCAT;
    if (idx < total) {
        int k = idx / NCAT;
        int c = idx - k * NCAT;
        float v;
        if      (c < 256) v = w00_l1_W[k * 256 + c];
        else if (c < 512) v = w1_l1_W[k * 256 + (c - 256)];
        else if (c < 768) v = w2_l1_W[k * 256 + (c - 512)];
        else if (c < 778) v = w01_W[k * 10 + (c - 768)];
        else if (c == 778) v = b01_W[k];
        else if (c == 779) v = b00_W[k];
        else if (c < 812) v = b1_W[k * 32 + (c - 780)];
        else              v = b2_l1_W[k * 32 + (c - 812)];
        g_Bcat[idx] = v;
    }
    if (idx < NCAT) {
        int c = idx;
        float v;
        if      (c < 256) v = w00_l1_b[c];
        else if (c < 512) v = w1_l1_b[c - 256];
        else if (c < 768) v = w2_l1_b[c - 512];
        else if (c < 778) v = w01_b[c - 768];
        else if (c == 778) v = b01_b[0];
        else if (c == 779) v = b00_b[0];
        else if (c < 812) v = b1_b[c - 780];
        else              v = b2_l1_b[c - 812];
        g_biascat[c] = v;
    }
}

// deltas from the "all-ones onehot row" quirk: contributions of rows [512,528)
__global__ void delta_kernel(const float* __restrict__ w00_l1_W,
                             const float* __restrict__ b00_W)
{
    int t = threadIdx.x;
    if (t < Hh) {
        float s = 0.f;
        #pragma unroll
        for (int j = 0; j < NVv; j++) s += w00_l1_W[(SDd + j) * 256 + t];
        g_hdelta[t] = s;
    }
    if (t == 0) {
        float s = 0.f;
        #pragma unroll
        for (int j = 0; j < NVv; j++) s += b00_W[SDd + j];
        g_gdelta[0] = s;
    }
}

// ---------------------------------------------------------------------------
// Tiled fp32 GEMM with packed fma.rn.f32x2 (FFMA2) inner product.
// C[M x N] = op(A)[M x K] @ B[K x N] + bias[N]
// BM=128, BN=64, BK=16, 256 threads, 8x4 micro-tile per thread,
// accumulators held as 4 M-pairs x 4 N in 64-bit packed f32x2 registers.
// ---------------------------------------------------------------------------
template <bool RELU_A>
__global__ void __launch_bounds__(256)
gemm_kernel(const float* __restrict__ A, int lda,
            const float* __restrict__ B, int ldb,
            const float* __restrict__ bias,
            float* __restrict__ C, int ldc,
            int N, int K)
{
    __shared__ float As[16][128];   // transposed A tile: As[k][m]
    __shared__ float Bs[16][68];    // padded

    const int tid = threadIdx.x;
    const int tx = tid & 15;        // N direction (x4)
    const int ty = tid >> 4;        // M direction (x8)
    const int bm = blockIdx.y * 128;
    const int bn = blockIdx.x * 64;

    unsigned long long acc[4][4];   // [m_pair][n], each = packed (f32 lo, f32 hi)
    #pragma unroll
    for (int m = 0; m < 4; m++)
        #pragma unroll
        for (int n = 0; n < 4; n++) acc[m][n] = 0ull;

    const bool nfull = (bn + 64 <= N);
    const int arow0 = tid >> 2;
    const int acol  = (tid & 3) << 2;
    const int brow  = tid >> 4;
    const int bcol  = (tid & 15) << 2;

    for (int k0 = 0; k0 < K; k0 += 16) {
        // A tile: 128x16, each thread 2 float4 loads, store transposed
        #pragma unroll
        for (int i = 0; i < 2; i++) {
            int arow = arow0 + i * 64;
            float4 v = *(const float4*)(A + (size_t)(bm + arow) * lda + k0 + acol);
            if (RELU_A) {
                v.x = fmaxf(v.x, 0.f); v.y = fmaxf(v.y, 0.f);
                v.z = fmaxf(v.z, 0.f); v.w = fmaxf(v.w, 0.f);
            }
            As[acol + 0][arow] = v.x;
            As[acol + 1][arow] = v.y;
            As[acol + 2][arow] = v.z;
            As[acol + 3][arow] = v.w;
        }
        // B tile: 16x64, each thread one float4 (or guarded scalars on edge)
        if (nfull) {
            float4 v = *(const float4*)(B + (size_t)(k0 + brow) * ldb + bn + bcol);
            Bs[brow][bcol + 0] = v.x;
            Bs[brow][bcol + 1] = v.y;
            Bs[brow][bcol + 2] = v.z;
            Bs[brow][bcol + 3] = v.w;
        } else {
            #pragma unroll
            for (int j = 0; j < 4; j++) {
                int c = bn + bcol + j;
                Bs[brow][bcol + j] = (c < N) ? B[(size_t)(k0 + brow) * ldb + c] : 0.f;
            }
        }
        __syncthreads();

        #pragma unroll
        for (int kk = 0; kk < 16; kk++) {
            // A: 4 x 64-bit loads -> 8 consecutive M values (pairs)
            unsigned long long ra[4];
            #pragma unroll
            for (int m = 0; m < 4; m++)
                ra[m] = *(const unsigned long long*)&As[kk][ty * 8 + m * 2];
            // B: 4 scalars, each duplicated into both f32x2 lanes
            float2 rb01 = *(const float2*)&Bs[kk][tx * 4];
            float2 rb23 = *(const float2*)&Bs[kk][tx * 4 + 2];
            unsigned long long bb[4];
            asm("mov.b64 %0, {%1, %1};" : "=l"(bb[0]) : "f"(rb01.x));
            asm("mov.b64 %0, {%1, %1};" : "=l"(bb[1]) : "f"(rb01.y));
            asm("mov.b64 %0, {%1, %1};" : "=l"(bb[2]) : "f"(rb23.x));
            asm("mov.b64 %0, {%1, %1};" : "=l"(bb[3]) : "f"(rb23.y));
            #pragma unroll
            for (int m = 0; m < 4; m++)
                #pragma unroll
                for (int n = 0; n < 4; n++)
                    asm("fma.rn.f32x2 %0, %1, %2, %0;"
                        : "+l"(acc[m][n]) : "l"(ra[m]), "l"(bb[n]));
        }
        __syncthreads();
    }

    #pragma unroll
    for (int m = 0; m < 4; m++) {
        float lo[4], hi[4];
        #pragma unroll
        for (int n = 0; n < 4; n++)
            asm("mov.b64 {%0, %1}, %2;" : "=f"(lo[n]), "=f"(hi[n]) : "l"(acc[m][n]));
        int r0 = bm + ty * 8 + m * 2;
        #pragma unroll
        for (int n = 0; n < 4; n++) {
            int c = bn + tx * 4 + n;
            if (c < N) {
                float bv = bias[c];
                C[(size_t)r0 * ldc + c]       = lo[n] + bv;
                C[(size_t)(r0 + 1) * ldc + c] = hi[n] + bv;
            }
        }
    }
}

// ---------------------------------------------------------------------------
// Final fused kernel: one warp per row (b,t).
// ---------------------------------------------------------------------------
__global__ void __launch_bounds__(256)
final_kernel(const float* __restrict__ qvals,
             const int*   __restrict__ cr,
             const float* __restrict__ w00_l2_W,  // (256,4)
             const float* __restrict__ w00_l2_b,  // (4)
             const float* __restrict__ w2_l2_W,   // (256,32)
             const float* __restrict__ w2_l2_b,   // (32)
             const float* __restrict__ b2_l2_W,   // (32,1)
             const float* __restrict__ b2_l2_b,   // (1)
             float* __restrict__ out)
{
    __shared__ float s_h[8][Hh];
    __shared__ float s_a2[8][Hh];
    __shared__ float s_q[8][NAa];

    const int w = threadIdx.x >> 5;
    const int l = threadIdx.x & 31;
    const int r = blockIdx.x * 8 + w;
    const int b = r >> 6;                 // batch index (T = 64)
    const float* __restrict__ row = g_H1 + (size_t)r * NCAT;

    for (int i = l; i < Hh; i += 32) {
        s_h[w][i]  = row[i];
        s_a2[w][i] = fmaxf(row[512 + i], 0.f);
    }
    if (l < NAa) s_q[w][l] = qvals[r * NAa + l];
    __syncwarp();

    const bool mod = (b < NVv);

    // --- w00_l2: common + modified (only meaningful when mod) ---
    float acc0[4] = {0.f, 0.f, 0.f, 0.f};
    float accm[4] = {0.f, 0.f, 0.f, 0.f};
    for (int kk = l; kk < Hh; kk += 32) {
        float hb = s_h[w][kk];
        float h  = fmaxf(hb, 0.f);
        float hm = fmaxf(hb + g_hdelta[kk], 0.f);
        float4 wv = *(const float4*)(w00_l2_W + kk * 4);
        acc0[0] += h  * wv.x; acc0[1] += h  * wv.y; acc0[2] += h  * wv.z; acc0[3] += h  * wv.w;
        accm[0] += hm * wv.x; accm[1] += hm * wv.y; accm[2] += hm * wv.z; accm[3] += hm * wv.w;
    }
    #pragma unroll
    for (int o = 0; o < 4; o++) {
        #pragma unroll
        for (int off = 16; off; off >>= 1) {
            acc0[o] += __shfl_xor_sync(0xffffffffu, acc0[o], off);
            accm[o] += __shfl_xor_sync(0xffffffffu, accm[o], off);
        }
    }
    float w0c[4], w0m[4];
    #pragma unroll
    for (int o = 0; o < 4; o++) {
        w0c[o] = fabsf(acc0[o] + w00_l2_b[o]);
        w0m[o] = fabsf(accm[o] + w00_l2_b[o]);
    }

    // --- w2 = |relu(a2) @ w2_l2_W + b|, lane l = output channel ---
    float acc2 = 0.f;
    #pragma unroll 8
    for (int kk = 0; kk < Hh; kk++) acc2 += s_a2[w][kk] * w2_l2_W[kk * Ee + l];
    float w2a = fabsf(acc2 + w2_l2_b[l]);

    // --- b2 = relu(states@b2_l1 + b) @ b2_l2_W + b2_l2_b ---
    float xb2 = fmaxf(row[812 + l], 0.f) * b2_l2_W[l];
    #pragma unroll
    for (int off = 16; off; off >>= 1) xb2 += __shfl_xor_sync(0xffffffffu, xb2, off);
    float b2 = xb2 + b2_l2_b[0];

    // --- b1 (lane = emb channel) ---
    float b1v = row[780 + l];

    // --- group q-values (lanes 0..15 = variables) and residual mix (lane >=16) ---
    float gq_l;
    if (l < NVv) {
        const int* __restrict__ crr = cr + (size_t)r * (Kk * NVv);
        float g = 0.f;
        #pragma unroll
        for (int k = 0; k < Kk; k++) {
            int idx = crr[k * NVv + l];
            float wk = (mod && l == b) ? w0m[k] : w0c[k];
            g += s_q[w][idx] * wk;
        }
        g += row[779];
        if (mod && l == b) g += g_gdelta[0];
        gq_l = g;
    } else {
        float oth = row[778];
        #pragma unroll
        for (int a = 0; a < NAa; a++) oth += s_q[w][a] * row[768 + a];
        gq_l = oth;
    }

    // --- hidden = elu(gq @ |w1| + b1), lane = emb channel ---
    const float* __restrict__ w1r = g_W1F + (size_t)r * N2;
    float accH = b1v;
    #pragma unroll
    for (int v = 0; v <= NVv; v++) {
        float gqv = __shfl_sync(0xffffffffu, gq_l, v);
        accH += gqv * fabsf(w1r[v * Ee + l]);
    }
    float hidden = (accH > 0.f) ? accH : expm1f(accH);

    float part = hidden * w2a;
    #pragma unroll
    for (int off = 16; off; off >>= 1) part += __shfl_xor_sync(0xffffffffu, part, off);
    if (l == 0) out[r] = part + b2;
}

// ---------------------------------------------------------------------------
extern "C" void kernel_launch(void* const* d_in, const int* in_sizes, int n_in,
                              void* d_out, int out_size)
{
    const float* qvals    = (const float*)d_in[0];
    const int*   cr       = (const int*)  d_in[1];
    const float* states   = (const float*)d_in[2];
    const float* w00_l1_W = (const float*)d_in[3];
    const float* w00_l1_b = (const float*)d_in[4];
    const float* w00_l2_W = (const float*)d_in[5];
    const float* w00_l2_b = (const float*)d_in[6];
    const float* b00_W    = (const float*)d_in[7];
    const float* b00_b    = (const float*)d_in[8];
    const float* w01_W    = (const float*)d_in[9];
    const float* w01_b    = (const float*)d_in[10];
    const float* b01_W    = (const float*)d_in[11];
    const float* b01_b    = (const float*)d_in[12];
    const float* w1_l1_W  = (const float*)d_in[13];
    const float* w1_l1_b  = (const float*)d_in[14];
    const float* w1_l2_W  = (const float*)d_in[15];
    const float* w1_l2_b  = (const float*)d_in[16];
    const float* b1_W     = (const float*)d_in[17];
    const float* b1_b     = (const float*)d_in[18];
    const float* w2_l1_W  = (const float*)d_in[19];
    const float* w2_l1_b  = (const float*)d_in[20];
    const float* w2_l2_W  = (const float*)d_in[21];
    const float* w2_l2_b  = (const float*)d_in[22];
    const float* b2_l1_W  = (const float*)d_in[23];
    const float* b2_l1_b  = (const float*)d_in[24];
    const float* b2_l2_W  = (const float*)d_in[25];
    const float* b2_l2_b  = (const float*)d_in[26];
    float* out = (float*)d_out;

    float *H1, *W1F, *Bcat, *biascat;
    cudaGetSymbolAddress((void**)&H1,      g_H1);
    cudaGetSymbolAddress((void**)&W1F,     g_W1F);
    cudaGetSymbolAddress((void**)&Bcat,    g_Bcat);
    cudaGetSymbolAddress((void**)&biascat, g_biascat);

    // 1) pack weights + biases, compute onehot deltas
    pack_kernel<<<(SDd * NCAT + 255) / 256, 256>>>(
        w00_l1_W, w00_l1_b, w1_l1_W, w1_l1_b, w2_l1_W, w2_l1_b,
        w01_W, w01_b, b01_W, b01_b, b00_W, b00_b, b1_W, b1_b, b2_l1_W, b2_l1_b);
    delta_kernel<<<1, 256>>>(w00_l1_W, b00_W);

    // 2) GEMM1: H1 = states @ Bcat + biascat     (8192 x 512 x 844)
    {
        dim3 grid((NCAT + 63) / 64, ROWS / 128);
        gemm_kernel<false><<<grid, 256>>>(states, SDd, Bcat, NCAT, biascat,
                                          H1, NCAT, NCAT, SDd);
    }

    // 3) GEMM2: W1F = relu(H1[:,256:512]) @ w1_l2_W + w1_l2_b  (8192 x 256 x 544)
    {
        dim3 grid((N2 + 63) / 64, ROWS / 128);
        gemm_kernel<true><<<grid, 256>>>(H1 + 256, NCAT, w1_l2_W, N2, w1_l2_b,
                                         W1F, N2, N2, Hh);
    }

    // 4) fused epilogue: one warp per row
    final_kernel<<<ROWS / 8, 256>>>(qvals, cr,
                                    w00_l2_W, w00_l2_b,
                                    w2_l2_W, w2_l2_b,
                                    b2_l2_W, b2_l2_b,
                                    out);
}

// round 9
// speedup vs baseline: 2.1515x; 2.0759x over previous
#include <cuda_runtime.h>
#include <cuda_bf16.h>
#include <math.h>
#include <stdint.h>

// Problem dims
#define Bdim 128
#define Tdim 64
#define NAa  10
#define NVv  16
#define Kk   4
#define SDd  512
#define Hh   256
#define Ee   32
#define ROWS (Bdim * Tdim)        // 8192
#define NCAT 844                  // real concat width
#define NCATP 896                 // padded to 14*64
#define N2   544                  // (NV+1)*E
#define N2P  576                  // padded to 9*64

// ---------------- scratch (__device__ globals; no cudaMalloc) ----------------
__device__ float g_H1[(size_t)ROWS * NCAT];          // GEMM1 out (fp32)
__device__ float g_W1F[(size_t)ROWS * N2];           // GEMM2 out (fp32)
__device__ __align__(16) __nv_bfloat16 g_SThi[(size_t)ROWS * SDd];
__device__ __align__(16) __nv_bfloat16 g_STlo[(size_t)ROWS * SDd];
__device__ __align__(16) __nv_bfloat16 g_MIDhi[(size_t)ROWS * Hh];
__device__ __align__(16) __nv_bfloat16 g_MIDlo[(size_t)ROWS * Hh];
__device__ __align__(16) __nv_bfloat16 g_BThi[(size_t)NCATP * SDd];   // B^T GEMM1 [c][k]
__device__ __align__(16) __nv_bfloat16 g_BTlo[(size_t)NCATP * SDd];
__device__ __align__(16) __nv_bfloat16 g_B2Thi[(size_t)N2P * Hh];     // B^T GEMM2
__device__ __align__(16) __nv_bfloat16 g_B2Tlo[(size_t)N2P * Hh];
__device__ float g_biascat[NCATP];
__device__ float g_bias2[N2P];
__device__ float g_hdelta[Hh];
__device__ float g_gdelta[1];

// ---------------- helpers ----------------
__device__ __forceinline__ uint32_t smem_u32(const void* p) {
    uint32_t a;
    asm("{ .reg .u64 t; cvta.to.shared.u64 t, %1; cvt.u32.u64 %0, t; }" : "=r"(a) : "l"(p));
    return a;
}
__device__ __forceinline__ void ldsm_x4(uint32_t* r, uint32_t addr) {
    asm volatile("ldmatrix.sync.aligned.m8n8.x4.shared.b16 {%0,%1,%2,%3}, [%4];"
                 : "=r"(r[0]), "=r"(r[1]), "=r"(r[2]), "=r"(r[3]) : "r"(addr));
}
__device__ __forceinline__ void mma_bf16(float* c, const uint32_t* a, const uint32_t* b) {
    asm volatile("mma.sync.aligned.m16n8k16.row.col.f32.bf16.bf16.f32 "
                 "{%0,%1,%2,%3}, {%4,%5,%6,%7}, {%8,%9}, {%0,%1,%2,%3};"
                 : "+f"(c[0]), "+f"(c[1]), "+f"(c[2]), "+f"(c[3])
                 : "r"(a[0]), "r"(a[1]), "r"(a[2]), "r"(a[3]), "r"(b[0]), "r"(b[1]));
}

// ---------------- split states into bf16 hi/lo ----------------
__global__ void split_states(const float* __restrict__ s) {
    int i = blockIdx.x * blockDim.x + threadIdx.x;     // over ROWS*SDd/4
    if (i >= ROWS * SDd / 4) return;
    float4 v = ((const float4*)s)[i];
    __nv_bfloat16 h0 = __float2bfloat16(v.x), h1 = __float2bfloat16(v.y);
    __nv_bfloat16 h2 = __float2bfloat16(v.z), h3 = __float2bfloat16(v.w);
    __nv_bfloat16 l0 = __float2bfloat16(v.x - __bfloat162float(h0));
    __nv_bfloat16 l1 = __float2bfloat16(v.y - __bfloat162float(h1));
    __nv_bfloat16 l2 = __float2bfloat16(v.z - __bfloat162float(h2));
    __nv_bfloat16 l3 = __float2bfloat16(v.w - __bfloat162float(h3));
    uint32_t hA = (uint32_t)__bfloat16_as_ushort(h0) | ((uint32_t)__bfloat16_as_ushort(h1) << 16);
    uint32_t hB = (uint32_t)__bfloat16_as_ushort(h2) | ((uint32_t)__bfloat16_as_ushort(h3) << 16);
    uint32_t lA = (uint32_t)__bfloat16_as_ushort(l0) | ((uint32_t)__bfloat16_as_ushort(l1) << 16);
    uint32_t lB = (uint32_t)__bfloat16_as_ushort(l2) | ((uint32_t)__bfloat16_as_ushort(l3) << 16);
    ((uint2*)g_SThi)[i] = make_uint2(hA, hB);
    ((uint2*)g_STlo)[i] = make_uint2(lA, lB);
}

// ---------------- pack transposed + bf16-split weights ----------------
__global__ void pack1_kernel(
    const float* __restrict__ w00_l1_W, const float* __restrict__ w00_l1_b,
    const float* __restrict__ w1_l1_W,  const float* __restrict__ w1_l1_b,
    const float* __restrict__ w2_l1_W,  const float* __restrict__ w2_l1_b,
    const float* __restrict__ w01_W,    const float* __restrict__ w01_b,
    const float* __restrict__ b01_W,    const float* __restrict__ b01_b,
    const float* __restrict__ b00_W,    const float* __restrict__ b00_b,
    const float* __restrict__ b1_W,     const float* __restrict__ b1_b,
    const float* __restrict__ b2_l1_W,  const float* __restrict__ b2_l1_b)
{
    int idx = blockIdx.x * blockDim.x + threadIdx.x;   // over NCATP*SDd
    if (idx < NCATP * SDd) {
        int c = idx / SDd;
        int k = idx - c * SDd;
        float v = 0.f;
        if (c < NCAT) {
            if      (c < 256) v = w00_l1_W[k * 256 + c];
            else if (c < 512) v = w1_l1_W[k * 256 + (c - 256)];
            else if (c < 768) v = w2_l1_W[k * 256 + (c - 512)];
            else if (c < 778) v = w01_W[k * 10 + (c - 768)];
            else if (c == 778) v = b01_W[k];
            else if (c == 779) v = b00_W[k];
            else if (c < 812) v = b1_W[k * 32 + (c - 780)];
            else              v = b2_l1_W[k * 32 + (c - 812)];
        }
        __nv_bfloat16 h = __float2bfloat16(v);
        g_BThi[idx] = h;
        g_BTlo[idx] = __float2bfloat16(v - __bfloat162float(h));
    }
    if (idx < NCATP) {
        int c = idx;
        float v = 0.f;
        if (c < NCAT) {
            if      (c < 256) v = w00_l1_b[c];
            else if (c < 512) v = w1_l1_b[c - 256];
            else if (c < 768) v = w2_l1_b[c - 512];
            else if (c < 778) v = w01_b[c - 768];
            else if (c == 778) v = b01_b[0];
            else if (c == 779) v = b00_b[0];
            else if (c < 812) v = b1_b[c - 780];
            else              v = b2_l1_b[c - 812];
        }
        g_biascat[c] = v;
    }
}

__global__ void pack2_kernel(const float* __restrict__ w1_l2_W, const float* __restrict__ w1_l2_b)
{
    int idx = blockIdx.x * blockDim.x + threadIdx.x;   // over N2P*Hh
    if (idx < N2P * Hh) {
        int c = idx / Hh;
        int k = idx - c * Hh;
        float v = (c < N2) ? w1_l2_W[k * N2 + c] : 0.f;
        __nv_bfloat16 h = __float2bfloat16(v);
        g_B2Thi[idx] = h;
        g_B2Tlo[idx] = __float2bfloat16(v - __bfloat162float(h));
    }
    if (idx < N2P) g_bias2[idx] = (idx < N2) ? w1_l2_b[idx] : 0.f;
}

__global__ void delta_kernel(const float* __restrict__ w00_l1_W, const float* __restrict__ b00_W)
{
    int t = threadIdx.x;
    if (t < Hh) {
        float s = 0.f;
        #pragma unroll
        for (int j = 0; j < NVv; j++) s += w00_l1_W[(SDd + j) * 256 + t];
        g_hdelta[t] = s;
    }
    if (t == 0) {
        float s = 0.f;
        #pragma unroll
        for (int j = 0; j < NVv; j++) s += b00_W[SDd + j];
        g_gdelta[0] = s;
    }
}

// ---------------------------------------------------------------------------
// mma.sync bf16 GEMM:  C[128 x 64 tile] = (Ahi+Alo) @ (Bhi+Blo)^T  (3-term)
// 256 threads, 8 warps (4M x 2N), warp tile 32x32 (2x4 m16n8k16).
// SMEM rows padded: 64 bf16 data + 8 pad = 72 bf16 = 144 bytes (conflict-free).
// If WRITE_MID: also emit relu+bf16-split of cols [256,512) into g_MID*.
// ---------------------------------------------------------------------------
#define SROW    144                     // bytes per smem row (64 bf16 + 16B pad)
#define OF_AHI  0
#define OF_ALO  (128 * SROW)            // 18432
#define OF_BHI  (2 * 128 * SROW)        // 36864
#define OF_BLO  (OF_BHI + 64 * SROW)    // 46080
#define SMTOT   (OF_BLO + 64 * SROW)    // 55296

template <bool WRITE_MID>
__global__ void __launch_bounds__(256)
gemm_mma(const __nv_bfloat16* __restrict__ Ahi, const __nv_bfloat16* __restrict__ Alo, int lda,
         const __nv_bfloat16* __restrict__ Bhi, const __nv_bfloat16* __restrict__ Blo,
         const float* __restrict__ bias,
         float* __restrict__ C, int ldc, int Nvalid, int K)
{
    extern __shared__ char smem[];
    const uint32_t sb = smem_u32(smem);
    const int tid  = threadIdx.x;
    const int w    = tid >> 5;
    const int lane = tid & 31;
    const int wm   = w & 3;           // 4 M groups of 32 rows
    const int wn   = w >> 2;          // 2 N groups of 32 cols
    const int bm   = blockIdx.y * 128;
    const int bn   = blockIdx.x * 64;

    float acc[2][4][4];
    #pragma unroll
    for (int mt = 0; mt < 2; mt++)
        #pragma unroll
        for (int nt = 0; nt < 4; nt++)
            #pragma unroll
            for (int i = 0; i < 4; i++) acc[mt][nt][i] = 0.f;

    for (int k0 = 0; k0 < K; k0 += 64) {
        // A tiles: 128 rows x 64 bf16 (hi & lo)
        #pragma unroll
        for (int i = 0; i < 4; i++) {
            int lin = i * 256 + tid;
            int row = lin >> 3, sec = lin & 7;
            const size_t go = (size_t)(bm + row) * lda + k0 + sec * 8;
            *(uint4*)(smem + OF_AHI + row * SROW + sec * 16) = *(const uint4*)(Ahi + go);
            *(uint4*)(smem + OF_ALO + row * SROW + sec * 16) = *(const uint4*)(Alo + go);
        }
        // B tiles: 64 rows x 64 bf16 (hi & lo)
        #pragma unroll
        for (int i = 0; i < 2; i++) {
            int lin = i * 256 + tid;
            int row = lin >> 3, sec = lin & 7;
            const size_t go = (size_t)(bn + row) * K + k0 + sec * 8;
            *(uint4*)(smem + OF_BHI + row * SROW + sec * 16) = *(const uint4*)(Bhi + go);
            *(uint4*)(smem + OF_BLO + row * SROW + sec * 16) = *(const uint4*)(Blo + go);
        }
        __syncthreads();

        #pragma unroll
        for (int ks = 0; ks < 4; ks++) {
            // A fragments (hi & lo) for 2 m16 tiles
            uint32_t ah[2][4], al[2][4];
            #pragma unroll
            for (int mt = 0; mt < 2; mt++) {
                int arow = wm * 32 + mt * 16 + (lane & 15);
                int akof = ks * 16 + (lane >> 4) * 8;
                uint32_t off = (uint32_t)(arow * SROW + akof * 2);
                ldsm_x4(ah[mt], sb + OF_AHI + off);
                ldsm_x4(al[mt], sb + OF_ALO + off);
            }
            // B fragments (hi & lo) for 4 n8 tiles (2 ldmatrix.x4 each part)
            uint32_t bh[4][2], bl[4][2];
            #pragma unroll
            for (int jp = 0; jp < 2; jp++) {
                int tilei = lane >> 3, rin = lane & 7;
                int nrow = wn * 32 + jp * 16 + (tilei >> 1) * 8 + rin;
                int kof  = ks * 16 + (tilei & 1) * 8;
                uint32_t off = (uint32_t)(nrow * SROW + kof * 2);
                uint32_t r[4];
                ldsm_x4(r, sb + OF_BHI + off);
                bh[jp*2][0] = r[0]; bh[jp*2][1] = r[1];
                bh[jp*2+1][0] = r[2]; bh[jp*2+1][1] = r[3];
                ldsm_x4(r, sb + OF_BLO + off);
                bl[jp*2][0] = r[0]; bl[jp*2][1] = r[1];
                bl[jp*2+1][0] = r[2]; bl[jp*2+1][1] = r[3];
            }
            #pragma unroll
            for (int mt = 0; mt < 2; mt++)
                #pragma unroll
                for (int nt = 0; nt < 4; nt++) {
                    mma_bf16(acc[mt][nt], ah[mt], bh[nt]);
                    mma_bf16(acc[mt][nt], ah[mt], bl[nt]);
                    mma_bf16(acc[mt][nt], al[mt], bh[nt]);
                }
        }
        __syncthreads();
    }

    // Epilogue: c0,c1 -> (row t/4, col (t%4)*2 + {0,1}); c2,c3 -> row+8
    const int trow  = lane >> 2;
    const int tcol2 = (lane & 3) * 2;
    #pragma unroll
    for (int mt = 0; mt < 2; mt++) {
        #pragma unroll
        for (int nt = 0; nt < 4; nt++) {
            int col = bn + wn * 32 + nt * 8 + tcol2;
            float bv0 = bias[col], bv1 = bias[col + 1];
            #pragma unroll
            for (int half = 0; half < 2; half++) {
                int row = bm + wm * 32 + mt * 16 + trow + half * 8;
                float v0 = acc[mt][nt][half * 2 + 0] + bv0;
                float v1 = acc[mt][nt][half * 2 + 1] + bv1;
                if (col < Nvalid)
                    *(float2*)(C + (size_t)row * ldc + col) = make_float2(v0, v1);
                if (WRITE_MID && col >= 256 && col < 512) {
                    float r0 = fmaxf(v0, 0.f), r1 = fmaxf(v1, 0.f);
                    __nv_bfloat16 h0 = __float2bfloat16(r0), h1 = __float2bfloat16(r1);
                    __nv_bfloat16 l0 = __float2bfloat16(r0 - __bfloat162float(h0));
                    __nv_bfloat16 l1 = __float2bfloat16(r1 - __bfloat162float(h1));
                    uint32_t ph = (uint32_t)__bfloat16_as_ushort(h0) | ((uint32_t)__bfloat16_as_ushort(h1) << 16);
                    uint32_t pl = (uint32_t)__bfloat16_as_ushort(l0) | ((uint32_t)__bfloat16_as_ushort(l1) << 16);
                    size_t mo = ((size_t)row * Hh + (col - 256)) >> 1;
                    ((uint32_t*)g_MIDhi)[mo] = ph;
                    ((uint32_t*)g_MIDlo)[mo] = pl;
                }
            }
        }
    }
}

// ---------------------------------------------------------------------------
// Final fused kernel: one warp per row (b,t).
// ---------------------------------------------------------------------------
__global__ void __launch_bounds__(256)
final_kernel(const float* __restrict__ qvals,
             const int*   __restrict__ cr,
             const float* __restrict__ w00_l2_W,  // (256,4)
             const float* __restrict__ w00_l2_b,  // (4)
             const float* __restrict__ w2_l2_W,   // (256,32)
             const float* __restrict__ w2_l2_b,   // (32)
             const float* __restrict__ b2_l2_W,   // (32,1)
             const float* __restrict__ b2_l2_b,   // (1)
             float* __restrict__ out)
{
    __shared__ float s_h[8][Hh];
    __shared__ float s_a2[8][Hh];
    __shared__ float s_q[8][NAa];

    const int w = threadIdx.x >> 5;
    const int l = threadIdx.x & 31;
    const int r = blockIdx.x * 8 + w;
    const int b = r >> 6;                 // batch index (T = 64)
    const float* __restrict__ row = g_H1 + (size_t)r * NCAT;

    for (int i = l; i < Hh; i += 32) {
        s_h[w][i]  = row[i];
        s_a2[w][i] = fmaxf(row[512 + i], 0.f);
    }
    if (l < NAa) s_q[w][l] = qvals[r * NAa + l];
    __syncwarp();

    const bool mod = (b < NVv);

    float acc0[4] = {0.f, 0.f, 0.f, 0.f};
    float accm[4] = {0.f, 0.f, 0.f, 0.f};
    for (int kk = l; kk < Hh; kk += 32) {
        float hb = s_h[w][kk];
        float h  = fmaxf(hb, 0.f);
        float hm = fmaxf(hb + g_hdelta[kk], 0.f);
        float4 wv = *(const float4*)(w00_l2_W + kk * 4);
        acc0[0] += h  * wv.x; acc0[1] += h  * wv.y; acc0[2] += h  * wv.z; acc0[3] += h  * wv.w;
        accm[0] += hm * wv.x; accm[1] += hm * wv.y; accm[2] += hm * wv.z; accm[3] += hm * wv.w;
    }
    #pragma unroll
    for (int o = 0; o < 4; o++) {
        #pragma unroll
        for (int off = 16; off; off >>= 1) {
            acc0[o] += __shfl_xor_sync(0xffffffffu, acc0[o], off);
            accm[o] += __shfl_xor_sync(0xffffffffu, accm[o], off);
        }
    }
    float w0c[4], w0m[4];
    #pragma unroll
    for (int o = 0; o < 4; o++) {
        w0c[o] = fabsf(acc0[o] + w00_l2_b[o]);
        w0m[o] = fabsf(accm[o] + w00_l2_b[o]);
    }

    float acc2 = 0.f;
    #pragma unroll 8
    for (int kk = 0; kk < Hh; kk++) acc2 += s_a2[w][kk] * w2_l2_W[kk * Ee + l];
    float w2a = fabsf(acc2 + w2_l2_b[l]);

    float xb2 = fmaxf(row[812 + l], 0.f) * b2_l2_W[l];
    #pragma unroll
    for (int off = 16; off; off >>= 1) xb2 += __shfl_xor_sync(0xffffffffu, xb2, off);
    float b2 = xb2 + b2_l2_b[0];

    float b1v = row[780 + l];

    float gq_l;
    if (l < NVv) {
        const int* __restrict__ crr = cr + (size_t)r * (Kk * NVv);
        float g = 0.f;
        #pragma unroll
        for (int k = 0; k < Kk; k++) {
            int idx = crr[k * NVv + l];
            float wk = (mod && l == b) ? w0m[k] : w0c[k];
            g += s_q[w][idx] * wk;
        }
        g += row[779];
        if (mod && l == b) g += g_gdelta[0];
        gq_l = g;
    } else {
        float oth = row[778];
        #pragma unroll
        for (int a = 0; a < NAa; a++) oth += s_q[w][a] * row[768 + a];
        gq_l = oth;
    }

    const float* __restrict__ w1r = g_W1F + (size_t)r * N2;
    float accH = b1v;
    #pragma unroll
    for (int v = 0; v <= NVv; v++) {
        float gqv = __shfl_sync(0xffffffffu, gq_l, v);
        accH += gqv * fabsf(w1r[v * Ee + l]);
    }
    float hidden = (accH > 0.f) ? accH : expm1f(accH);

    float part = hidden * w2a;
    #pragma unroll
    for (int off = 16; off; off >>= 1) part += __shfl_xor_sync(0xffffffffu, part, off);
    if (l == 0) out[r] = part + b2;
}

// ---------------------------------------------------------------------------
extern "C" void kernel_launch(void* const* d_in, const int* in_sizes, int n_in,
                              void* d_out, int out_size)
{
    const float* qvals    = (const float*)d_in[0];
    const int*   cr       = (const int*)  d_in[1];
    const float* states   = (const float*)d_in[2];
    const float* w00_l1_W = (const float*)d_in[3];
    const float* w00_l1_b = (const float*)d_in[4];
    const float* w00_l2_W = (const float*)d_in[5];
    const float* w00_l2_b = (const float*)d_in[6];
    const float* b00_W    = (const float*)d_in[7];
    const float* b00_b    = (const float*)d_in[8];
    const float* w01_W    = (const float*)d_in[9];
    const float* w01_b    = (const float*)d_in[10];
    const float* b01_W    = (const float*)d_in[11];
    const float* b01_b    = (const float*)d_in[12];
    const float* w1_l1_W  = (const float*)d_in[13];
    const float* w1_l1_b  = (const float*)d_in[14];
    const float* w1_l2_W  = (const float*)d_in[15];
    const float* w1_l2_b  = (const float*)d_in[16];
    const float* b1_W     = (const float*)d_in[17];
    const float* b1_b     = (const float*)d_in[18];
    const float* w2_l1_W  = (const float*)d_in[19];
    const float* w2_l1_b  = (const float*)d_in[20];
    const float* w2_l2_W  = (const float*)d_in[21];
    const float* w2_l2_b  = (const float*)d_in[22];
    const float* b2_l1_W  = (const float*)d_in[23];
    const float* b2_l1_b  = (const float*)d_in[24];
    const float* b2_l2_W  = (const float*)d_in[25];
    const float* b2_l2_b  = (const float*)d_in[26];
    float* out = (float*)d_out;

    static int attr_done = 0;
    if (!attr_done) {
        cudaFuncSetAttribute(gemm_mma<true>,  cudaFuncAttributeMaxDynamicSharedMemorySize, SMTOT);
        cudaFuncSetAttribute(gemm_mma<false>, cudaFuncAttributeMaxDynamicSharedMemorySize, SMTOT);
        attr_done = 1;
    }

    float *H1, *W1F, *biascat, *bias2;
    __nv_bfloat16 *SThi, *STlo, *MIDhi, *MIDlo, *BThi, *BTlo, *B2Thi, *B2Tlo;
    cudaGetSymbolAddress((void**)&H1,      g_H1);
    cudaGetSymbolAddress((void**)&W1F,     g_W1F);
    cudaGetSymbolAddress((void**)&biascat, g_biascat);
    cudaGetSymbolAddress((void**)&bias2,   g_bias2);
    cudaGetSymbolAddress((void**)&SThi,    g_SThi);
    cudaGetSymbolAddress((void**)&STlo,    g_STlo);
    cudaGetSymbolAddress((void**)&MIDhi,   g_MIDhi);
    cudaGetSymbolAddress((void**)&MIDlo,   g_MIDlo);
    cudaGetSymbolAddress((void**)&BThi,    g_BThi);
    cudaGetSymbolAddress((void**)&BTlo,    g_BTlo);
    cudaGetSymbolAddress((void**)&B2Thi,   g_B2Thi);
    cudaGetSymbolAddress((void**)&B2Tlo,   g_B2Tlo);

    // 1) precompute: bf16 splits + transposed packed weights + deltas
    split_states<<<(ROWS * SDd / 4 + 255) / 256, 256>>>(states);
    pack1_kernel<<<(NCATP * SDd + 255) / 256, 256>>>(
        w00_l1_W, w00_l1_b, w1_l1_W, w1_l1_b, w2_l1_W, w2_l1_b,
        w01_W, w01_b, b01_W, b01_b, b00_W, b00_b, b1_W, b1_b, b2_l1_W, b2_l1_b);
    pack2_kernel<<<(N2P * Hh + 255) / 256, 256>>>(w1_l2_W, w1_l2_b);
    delta_kernel<<<1, 256>>>(w00_l1_W, b00_W);

    // 2) GEMM1 (mma.sync bf16x3): H1 = states @ Bcat + bias; fused relu+split mid
    {
        dim3 grid(NCATP / 64, ROWS / 128);
        gemm_mma<true><<<grid, 256, SMTOT>>>(SThi, STlo, SDd, BThi, BTlo,
                                             biascat, H1, NCAT, NCAT, SDd);
    }

    // 3) GEMM2 (mma.sync bf16x3): W1F = relu(H1mid) @ w1_l2 + bias
    {
        dim3 grid(N2P / 64, ROWS / 128);
        gemm_mma<false><<<grid, 256, SMTOT>>>(MIDhi, MIDlo, Hh, B2Thi, B2Tlo,
                                              bias2, W1F, N2, N2, Hh);
    }

    // 4) fused epilogue: one warp per row
    final_kernel<<<ROWS / 8, 256>>>(qvals, cr,
                                    w00_l2_W, w00_l2_b,
                                    w2_l2_W, w2_l2_b,
                                    b2_l2_W, b2_l2_b,
                                    out);
}

// round 10
// speedup vs baseline: 2.1737x; 1.0103x over previous
#include <cuda_runtime.h>
#include <cuda_bf16.h>
#include <math.h>
#include <stdint.h>

// Problem dims
#define Bdim 128
#define Tdim 64
#define NAa  10
#define NVv  16
#define Kk   4
#define SDd  512
#define Hh   256
#define Ee   32
#define ROWS (Bdim * Tdim)        // 8192
#define NCAT 844                  // real concat width
#define NCATP 896                 // padded to 14*64
#define N2   544                  // (NV+1)*E
#define N2P  576                  // padded to 9*64

// ---------------- scratch (__device__ globals; no cudaMalloc) ----------------
__device__ float g_H1[(size_t)ROWS * NCAT];          // GEMM1 out (fp32)
__device__ float g_W1F[(size_t)ROWS * N2];           // GEMM2 out (fp32)
__device__ __align__(16) __nv_bfloat16 g_SThi[(size_t)ROWS * SDd];
__device__ __align__(16) __nv_bfloat16 g_STlo[(size_t)ROWS * SDd];
__device__ __align__(16) __nv_bfloat16 g_MIDhi[(size_t)ROWS * Hh];
__device__ __align__(16) __nv_bfloat16 g_MIDlo[(size_t)ROWS * Hh];
__device__ __align__(16) __nv_bfloat16 g_BThi[(size_t)NCATP * SDd];   // B^T GEMM1 [c][k]
__device__ __align__(16) __nv_bfloat16 g_BTlo[(size_t)NCATP * SDd];
__device__ __align__(16) __nv_bfloat16 g_B2Thi[(size_t)N2P * Hh];     // B^T GEMM2
__device__ __align__(16) __nv_bfloat16 g_B2Tlo[(size_t)N2P * Hh];
__device__ float g_biascat[NCATP];
__device__ float g_bias2[N2P];
__device__ float g_hdelta[Hh];
__device__ float g_gdelta[1];

// ---------------- helpers ----------------
__device__ __forceinline__ uint32_t smem_u32(const void* p) {
    uint32_t a;
    asm("{ .reg .u64 t; cvta.to.shared.u64 t, %1; cvt.u32.u64 %0, t; }" : "=r"(a) : "l"(p));
    return a;
}
__device__ __forceinline__ void ldsm_x4(uint32_t* r, uint32_t addr) {
    asm volatile("ldmatrix.sync.aligned.m8n8.x4.shared.b16 {%0,%1,%2,%3}, [%4];"
                 : "=r"(r[0]), "=r"(r[1]), "=r"(r[2]), "=r"(r[3]) : "r"(addr));
}
__device__ __forceinline__ void mma_bf16(float* c, const uint32_t* a, const uint32_t* b) {
    asm volatile("mma.sync.aligned.m16n8k16.row.col.f32.bf16.bf16.f32 "
                 "{%0,%1,%2,%3}, {%4,%5,%6,%7}, {%8,%9}, {%0,%1,%2,%3};"
                 : "+f"(c[0]), "+f"(c[1]), "+f"(c[2]), "+f"(c[3])
                 : "r"(a[0]), "r"(a[1]), "r"(a[2]), "r"(a[3]), "r"(b[0]), "r"(b[1]));
}
#define CP_ASYNC16(dst, src) \
    asm volatile("cp.async.cg.shared.global [%0], [%1], 16;" :: "r"(dst), "l"(src))
#define CP_COMMIT() asm volatile("cp.async.commit_group;" ::: "memory")
#define CP_WAIT(n)  asm volatile("cp.async.wait_group %0;" :: "n"(n) : "memory")

// ---------------- split states into bf16 hi/lo ----------------
__global__ void split_states(const float* __restrict__ s) {
    int i = blockIdx.x * blockDim.x + threadIdx.x;     // over ROWS*SDd/4
    if (i >= ROWS * SDd / 4) return;
    float4 v = ((const float4*)s)[i];
    __nv_bfloat16 h0 = __float2bfloat16(v.x), h1 = __float2bfloat16(v.y);
    __nv_bfloat16 h2 = __float2bfloat16(v.z), h3 = __float2bfloat16(v.w);
    __nv_bfloat16 l0 = __float2bfloat16(v.x - __bfloat162float(h0));
    __nv_bfloat16 l1 = __float2bfloat16(v.y - __bfloat162float(h1));
    __nv_bfloat16 l2 = __float2bfloat16(v.z - __bfloat162float(h2));
    __nv_bfloat16 l3 = __float2bfloat16(v.w - __bfloat162float(h3));
    uint32_t hA = (uint32_t)__bfloat16_as_ushort(h0) | ((uint32_t)__bfloat16_as_ushort(h1) << 16);
    uint32_t hB = (uint32_t)__bfloat16_as_ushort(h2) | ((uint32_t)__bfloat16_as_ushort(h3) << 16);
    uint32_t lA = (uint32_t)__bfloat16_as_ushort(l0) | ((uint32_t)__bfloat16_as_ushort(l1) << 16);
    uint32_t lB = (uint32_t)__bfloat16_as_ushort(l2) | ((uint32_t)__bfloat16_as_ushort(l3) << 16);
    ((uint2*)g_SThi)[i] = make_uint2(hA, hB);
    ((uint2*)g_STlo)[i] = make_uint2(lA, lB);
}

// ---------------- pack transposed + bf16-split weights (+ fused deltas) ----------------
__global__ void pack1_kernel(
    const float* __restrict__ w00_l1_W, const float* __restrict__ w00_l1_b,
    const float* __restrict__ w1_l1_W,  const float* __restrict__ w1_l1_b,
    const float* __restrict__ w2_l1_W,  const float* __restrict__ w2_l1_b,
    const float* __restrict__ w01_W,    const float* __restrict__ w01_b,
    const float* __restrict__ b01_W,    const float* __restrict__ b01_b,
    const float* __restrict__ b00_W,    const float* __restrict__ b00_b,
    const float* __restrict__ b1_W,     const float* __restrict__ b1_b,
    const float* __restrict__ b2_l1_W,  const float* __restrict__ b2_l1_b)
{
    int idx = blockIdx.x * blockDim.x + threadIdx.x;   // over NCATP*SDd
    if (idx < NCATP * SDd) {
        int c = idx / SDd;
        int k = idx - c * SDd;
        float v = 0.f;
        if (c < NCAT) {
            if      (c < 256) v = w00_l1_W[k * 256 + c];
            else if (c < 512) v = w1_l1_W[k * 256 + (c - 256)];
            else if (c < 768) v = w2_l1_W[k * 256 + (c - 512)];
            else if (c < 778) v = w01_W[k * 10 + (c - 768)];
            else if (c == 778) v = b01_W[k];
            else if (c == 779) v = b00_W[k];
            else if (c < 812) v = b1_W[k * 32 + (c - 780)];
            else              v = b2_l1_W[k * 32 + (c - 812)];
        }
        __nv_bfloat16 h = __float2bfloat16(v);
        g_BThi[idx] = h;
        g_BTlo[idx] = __float2bfloat16(v - __bfloat162float(h));
    }
    if (idx < NCATP) {
        int c = idx;
        float v = 0.f;
        if (c < NCAT) {
            if      (c < 256) v = w00_l1_b[c];
            else if (c < 512) v = w1_l1_b[c - 256];
            else if (c < 768) v = w2_l1_b[c - 512];
            else if (c < 778) v = w01_b[c - 768];
            else if (c == 778) v = b01_b[0];
            else if (c == 779) v = b00_b[0];
            else if (c < 812) v = b1_b[c - 780];
            else              v = b2_l1_b[c - 812];
        }
        g_biascat[c] = v;
    }
    // fused "all-ones onehot row" deltas
    if (idx < Hh) {
        float s = 0.f;
        #pragma unroll
        for (int j = 0; j < NVv; j++) s += w00_l1_W[(SDd + j) * 256 + idx];
        g_hdelta[idx] = s;
    }
    if (idx == Hh) {
        float s = 0.f;
        #pragma unroll
        for (int j = 0; j < NVv; j++) s += b00_W[SDd + j];
        g_gdelta[0] = s;
    }
}

__global__ void pack2_kernel(const float* __restrict__ w1_l2_W, const float* __restrict__ w1_l2_b)
{
    int idx = blockIdx.x * blockDim.x + threadIdx.x;   // over N2P*Hh
    if (idx < N2P * Hh) {
        int c = idx / Hh;
        int k = idx - c * Hh;
        float v = (c < N2) ? w1_l2_W[k * N2 + c] : 0.f;
        __nv_bfloat16 h = __float2bfloat16(v);
        g_B2Thi[idx] = h;
        g_B2Tlo[idx] = __float2bfloat16(v - __bfloat162float(h));
    }
    if (idx < N2P) g_bias2[idx] = (idx < N2) ? w1_l2_b[idx] : 0.f;
}

// ---------------------------------------------------------------------------
// mma.sync bf16 GEMM, 2-stage cp.async pipeline.
// C[128 x 64 tile] = (Ahi+Alo) @ (Bhi+Blo)^T  (3-term split)
// 256 threads, 8 warps (4M x 2N), warp tile 32x32 (2x4 m16n8k16).
// SMEM rows: 64 bf16 + 16B pad = 144 bytes (conflict-free ldmatrix).
// WRITE_MID: cols [256,512) -> relu+split to g_MID*, fp32 store skipped.
// ---------------------------------------------------------------------------
#define SROW    144
#define OF_AHI  0
#define OF_ALO  (128 * SROW)            // 18432
#define OF_BHI  (2 * 128 * SROW)        // 36864
#define OF_BLO  (OF_BHI + 64 * SROW)    // 46080
#define STAGE   (OF_BLO + 64 * SROW)    // 55296
#define SMTOT   (2 * STAGE)             // 110592

template <bool WRITE_MID>
__global__ void __launch_bounds__(256)
gemm_mma(const __nv_bfloat16* __restrict__ Ahi, const __nv_bfloat16* __restrict__ Alo, int lda,
         const __nv_bfloat16* __restrict__ Bhi, const __nv_bfloat16* __restrict__ Blo,
         const float* __restrict__ bias,
         float* __restrict__ C, int ldc, int Nvalid, int K)
{
    extern __shared__ char smem[];
    const uint32_t sb = smem_u32(smem);
    const int tid  = threadIdx.x;
    const int w    = tid >> 5;
    const int lane = tid & 31;
    const int wm   = w & 3;
    const int wn   = w >> 2;
    const int bm   = blockIdx.y * 128;
    const int bn   = blockIdx.x * 64;

    float acc[2][4][4];
    #pragma unroll
    for (int mt = 0; mt < 2; mt++)
        #pragma unroll
        for (int nt = 0; nt < 4; nt++)
            #pragma unroll
            for (int i = 0; i < 4; i++) acc[mt][nt][i] = 0.f;

    const int nch = K >> 6;
    const int arow = tid >> 3, asec = tid & 7;   // reused lin decompositions

    // ---- pipeline: issue loads for chunk c into stage s ----
    #define ISSUE_LOADS(c_, s_) do {                                             \
        const int k0_ = (c_) << 6;                                               \
        const uint32_t base_ = sb + (s_) * STAGE;                                \
        _Pragma("unroll")                                                        \
        for (int i = 0; i < 4; i++) {                                            \
            int row_ = arow + i * 32;                                            \
            uint32_t so_ = base_ + row_ * SROW + asec * 16;                      \
            const size_t go_ = (size_t)(bm + row_) * lda + k0_ + asec * 8;       \
            CP_ASYNC16(so_ + OF_AHI, (const char*)(Ahi + go_));                  \
            CP_ASYNC16(so_ + OF_ALO, (const char*)(Alo + go_));                  \
        }                                                                        \
        _Pragma("unroll")                                                        \
        for (int i = 0; i < 2; i++) {                                            \
            int row_ = arow + i * 32;                                            \
            uint32_t so_ = base_ + row_ * SROW + asec * 16;                      \
            const size_t go_ = (size_t)(bn + row_) * K + k0_ + asec * 8;         \
            CP_ASYNC16(so_ + OF_BHI, (const char*)(Bhi + go_));                  \
            CP_ASYNC16(so_ + OF_BLO, (const char*)(Blo + go_));                  \
        }                                                                        \
        CP_COMMIT();                                                             \
    } while (0)

    ISSUE_LOADS(0, 0);

    for (int c = 0; c < nch; c++) {
        if (c + 1 < nch) { ISSUE_LOADS(c + 1, (c + 1) & 1); CP_WAIT(1); }
        else             { CP_WAIT(0); }
        __syncthreads();

        const uint32_t stb = sb + (c & 1) * STAGE;
        #pragma unroll
        for (int ks = 0; ks < 4; ks++) {
            uint32_t ah[2][4], al[2][4];
            #pragma unroll
            for (int mt = 0; mt < 2; mt++) {
                int ar = wm * 32 + mt * 16 + (lane & 15);
                int ak = ks * 16 + (lane >> 4) * 8;
                uint32_t off = (uint32_t)(ar * SROW + ak * 2);
                ldsm_x4(ah[mt], stb + OF_AHI + off);
                ldsm_x4(al[mt], stb + OF_ALO + off);
            }
            uint32_t bh[4][2], bl[4][2];
            #pragma unroll
            for (int jp = 0; jp < 2; jp++) {
                int tilei = lane >> 3, rin = lane & 7;
                int nrow = wn * 32 + jp * 16 + (tilei >> 1) * 8 + rin;
                int kof  = ks * 16 + (tilei & 1) * 8;
                uint32_t off = (uint32_t)(nrow * SROW + kof * 2);
                uint32_t r[4];
                ldsm_x4(r, stb + OF_BHI + off);
                bh[jp*2][0] = r[0]; bh[jp*2][1] = r[1];
                bh[jp*2+1][0] = r[2]; bh[jp*2+1][1] = r[3];
                ldsm_x4(r, stb + OF_BLO + off);
                bl[jp*2][0] = r[0]; bl[jp*2][1] = r[1];
                bl[jp*2+1][0] = r[2]; bl[jp*2+1][1] = r[3];
            }
            #pragma unroll
            for (int mt = 0; mt < 2; mt++)
                #pragma unroll
                for (int nt = 0; nt < 4; nt++) {
                    mma_bf16(acc[mt][nt], ah[mt], bh[nt]);
                    mma_bf16(acc[mt][nt], ah[mt], bl[nt]);
                    mma_bf16(acc[mt][nt], al[mt], bh[nt]);
                }
        }
        __syncthreads();
    }

    // Epilogue
    const int trow  = lane >> 2;
    const int tcol2 = (lane & 3) * 2;
    #pragma unroll
    for (int mt = 0; mt < 2; mt++) {
        #pragma unroll
        for (int nt = 0; nt < 4; nt++) {
            int col = bn + wn * 32 + nt * 8 + tcol2;
            float bv0 = bias[col], bv1 = bias[col + 1];
            #pragma unroll
            for (int half = 0; half < 2; half++) {
                int row = bm + wm * 32 + mt * 16 + trow + half * 8;
                float v0 = acc[mt][nt][half * 2 + 0] + bv0;
                float v1 = acc[mt][nt][half * 2 + 1] + bv1;
                bool is_mid = WRITE_MID && col >= 256 && col < 512;
                if (is_mid) {
                    float r0 = fmaxf(v0, 0.f), r1 = fmaxf(v1, 0.f);
                    __nv_bfloat16 h0 = __float2bfloat16(r0), h1 = __float2bfloat16(r1);
                    __nv_bfloat16 l0 = __float2bfloat16(r0 - __bfloat162float(h0));
                    __nv_bfloat16 l1 = __float2bfloat16(r1 - __bfloat162float(h1));
                    uint32_t ph = (uint32_t)__bfloat16_as_ushort(h0) | ((uint32_t)__bfloat16_as_ushort(h1) << 16);
                    uint32_t pl = (uint32_t)__bfloat16_as_ushort(l0) | ((uint32_t)__bfloat16_as_ushort(l1) << 16);
                    size_t mo = ((size_t)row * Hh + (col - 256)) >> 1;
                    ((uint32_t*)g_MIDhi)[mo] = ph;
                    ((uint32_t*)g_MIDlo)[mo] = pl;
                } else if (col < Nvalid) {
                    *(float2*)(C + (size_t)row * ldc + col) = make_float2(v0, v1);
                }
            }
        }
    }
}

// ---------------------------------------------------------------------------
// Final fused kernel: one warp per row; w2_l2_W staged in SMEM per block.
// ---------------------------------------------------------------------------
__global__ void __launch_bounds__(256)
final_kernel(const float* __restrict__ qvals,
             const int*   __restrict__ cr,
             const float* __restrict__ w00_l2_W,  // (256,4)
             const float* __restrict__ w00_l2_b,  // (4)
             const float* __restrict__ w2_l2_W,   // (256,32)
             const float* __restrict__ w2_l2_b,   // (32)
             const float* __restrict__ b2_l2_W,   // (32,1)
             const float* __restrict__ b2_l2_b,   // (1)
             float* __restrict__ out)
{
    __shared__ float s_a2[8][Hh];
    __shared__ float s_q[8][NAa];
    __shared__ float s_w2[Hh * Ee];   // 32 KB

    const int w = threadIdx.x >> 5;
    const int l = threadIdx.x & 31;
    const int r = blockIdx.x * 8 + w;
    const int b = r >> 6;                 // batch index (T = 64)
    const float* __restrict__ row = g_H1 + (size_t)r * NCAT;

    // stage w2_l2_W (block-cooperative, vectorized)
    #pragma unroll
    for (int i = 0; i < 8; i++)
        ((float4*)s_w2)[i * 256 + threadIdx.x] = ((const float4*)w2_l2_W)[i * 256 + threadIdx.x];

    for (int i = l; i < Hh; i += 32)
        s_a2[w][i] = fmaxf(row[512 + i], 0.f);
    if (l < NAa) s_q[w][l] = qvals[r * NAa + l];
    __syncthreads();

    const bool mod = (b < NVv);

    // --- w00_l2: common + modified (reads H1 cols [0,256) straight from global)
    float acc0[4] = {0.f, 0.f, 0.f, 0.f};
    float accm[4] = {0.f, 0.f, 0.f, 0.f};
    for (int kk = l; kk < Hh; kk += 32) {
        float hb = row[kk];
        float h  = fmaxf(hb, 0.f);
        float hm = fmaxf(hb + g_hdelta[kk], 0.f);
        float4 wv = *(const float4*)(w00_l2_W + kk * 4);
        acc0[0] += h  * wv.x; acc0[1] += h  * wv.y; acc0[2] += h  * wv.z; acc0[3] += h  * wv.w;
        accm[0] += hm * wv.x; accm[1] += hm * wv.y; accm[2] += hm * wv.z; accm[3] += hm * wv.w;
    }
    #pragma unroll
    for (int o = 0; o < 4; o++) {
        #pragma unroll
        for (int off = 16; off; off >>= 1) {
            acc0[o] += __shfl_xor_sync(0xffffffffu, acc0[o], off);
            accm[o] += __shfl_xor_sync(0xffffffffu, accm[o], off);
        }
    }
    float w0c[4], w0m[4];
    #pragma unroll
    for (int o = 0; o < 4; o++) {
        w0c[o] = fabsf(acc0[o] + w00_l2_b[o]);
        w0m[o] = fabsf(accm[o] + w00_l2_b[o]);
    }

    // --- w2 = |relu(a2) @ w2_l2_W + b|, lane l = output channel (SMEM weights)
    float acc2 = 0.f;
    #pragma unroll 8
    for (int kk = 0; kk < Hh; kk++) acc2 += s_a2[w][kk] * s_w2[kk * Ee + l];
    float w2a = fabsf(acc2 + w2_l2_b[l]);

    // --- b2
    float xb2 = fmaxf(row[812 + l], 0.f) * b2_l2_W[l];
    #pragma unroll
    for (int off = 16; off; off >>= 1) xb2 += __shfl_xor_sync(0xffffffffu, xb2, off);
    float b2 = xb2 + b2_l2_b[0];

    float b1v = row[780 + l];

    // --- group q-values / residual mix
    float gq_l;
    if (l < NVv) {
        const int* __restrict__ crr = cr + (size_t)r * (Kk * NVv);
        float g = 0.f;
        #pragma unroll
        for (int k = 0; k < Kk; k++) {
            int idx = crr[k * NVv + l];
            float wk = (mod && l == b) ? w0m[k] : w0c[k];
            g += s_q[w][idx] * wk;
        }
        g += row[779];
        if (mod && l == b) g += g_gdelta[0];
        gq_l = g;
    } else {
        float oth = row[778];
        #pragma unroll
        for (int a = 0; a < NAa; a++) oth += s_q[w][a] * row[768 + a];
        gq_l = oth;
    }

    // --- hidden = elu(gq @ |w1| + b1)
    const float* __restrict__ w1r = g_W1F + (size_t)r * N2;
    float accH = b1v;
    #pragma unroll
    for (int v = 0; v <= NVv; v++) {
        float gqv = __shfl_sync(0xffffffffu, gq_l, v);
        accH += gqv * fabsf(w1r[v * Ee + l]);
    }
    float hidden = (accH > 0.f) ? accH : expm1f(accH);

    float part = hidden * w2a;
    #pragma unroll
    for (int off = 16; off; off >>= 1) part += __shfl_xor_sync(0xffffffffu, part, off);
    if (l == 0) out[r] = part + b2;
}

// ---------------------------------------------------------------------------
extern "C" void kernel_launch(void* const* d_in, const int* in_sizes, int n_in,
                              void* d_out, int out_size)
{
    const float* qvals    = (const float*)d_in[0];
    const int*   cr       = (const int*)  d_in[1];
    const float* states   = (const float*)d_in[2];
    const float* w00_l1_W = (const float*)d_in[3];
    const float* w00_l1_b = (const float*)d_in[4];
    const float* w00_l2_W = (const float*)d_in[5];
    const float* w00_l2_b = (const float*)d_in[6];
    const float* b00_W    = (const float*)d_in[7];
    const float* b00_b    = (const float*)d_in[8];
    const float* w01_W    = (const float*)d_in[9];
    const float* w01_b    = (const float*)d_in[10];
    const float* b01_W    = (const float*)d_in[11];
    const float* b01_b    = (const float*)d_in[12];
    const float* w1_l1_W  = (const float*)d_in[13];
    const float* w1_l1_b  = (const float*)d_in[14];
    const float* w1_l2_W  = (const float*)d_in[15];
    const float* w1_l2_b  = (const float*)d_in[16];
    const float* b1_W     = (const float*)d_in[17];
    const float* b1_b     = (const float*)d_in[18];
    const float* w2_l1_W  = (const float*)d_in[19];
    const float* w2_l1_b  = (const float*)d_in[20];
    const float* w2_l2_W  = (const float*)d_in[21];
    const float* w2_l2_b  = (const float*)d_in[22];
    const float* b2_l1_W  = (const float*)d_in[23];
    const float* b2_l1_b  = (const float*)d_in[24];
    const float* b2_l2_W  = (const float*)d_in[25];
    const float* b2_l2_b  = (const float*)d_in[26];
    float* out = (float*)d_out;

    static int attr_done = 0;
    if (!attr_done) {
        cudaFuncSetAttribute(gemm_mma<true>,  cudaFuncAttributeMaxDynamicSharedMemorySize, SMTOT);
        cudaFuncSetAttribute(gemm_mma<false>, cudaFuncAttributeMaxDynamicSharedMemorySize, SMTOT);
        attr_done = 1;
    }

    float *H1, *W1F, *biascat, *bias2;
    __nv_bfloat16 *SThi, *STlo, *MIDhi, *MIDlo, *BThi, *BTlo, *B2Thi, *B2Tlo;
    cudaGetSymbolAddress((void**)&H1,      g_H1);
    cudaGetSymbolAddress((void**)&W1F,     g_W1F);
    cudaGetSymbolAddress((void**)&biascat, g_biascat);
    cudaGetSymbolAddress((void**)&bias2,   g_bias2);
    cudaGetSymbolAddress((void**)&SThi,    g_SThi);
    cudaGetSymbolAddress((void**)&STlo,    g_STlo);
    cudaGetSymbolAddress((void**)&MIDhi,   g_MIDhi);
    cudaGetSymbolAddress((void**)&MIDlo,   g_MIDlo);
    cudaGetSymbolAddress((void**)&BThi,    g_BThi);
    cudaGetSymbolAddress((void**)&BTlo,    g_BTlo);
    cudaGetSymbolAddress((void**)&B2Thi,   g_B2Thi);
    cudaGetSymbolAddress((void**)&B2Tlo,   g_B2Tlo);

    // 1) precompute: bf16 splits + transposed packed weights (+deltas fused)
    split_states<<<(ROWS * SDd / 4 + 255) / 256, 256>>>(states);
    pack1_kernel<<<(NCATP * SDd + 255) / 256, 256>>>(
        w00_l1_W, w00_l1_b, w1_l1_W, w1_l1_b, w2_l1_W, w2_l1_b,
        w01_W, w01_b, b01_W, b01_b, b00_W, b00_b, b1_W, b1_b, b2_l1_W, b2_l1_b);
    pack2_kernel<<<(N2P * Hh + 255) / 256, 256>>>(w1_l2_W, w1_l2_b);

    // 2) GEMM1 (mma.sync bf16x3, cp.async pipelined)
    {
        dim3 grid(NCATP / 64, ROWS / 128);
        gemm_mma<true><<<grid, 256, SMTOT>>>(SThi, STlo, SDd, BThi, BTlo,
                                             biascat, H1, NCAT, NCAT, SDd);
    }

    // 3) GEMM2
    {
        dim3 grid(N2P / 64, ROWS / 128);
        gemm_mma<false><<<grid, 256, SMTOT>>>(MIDhi, MIDlo, Hh, B2Thi, B2Tlo,
                                              bias2, W1F, N2, N2, Hh);
    }

    // 4) fused epilogue
    final_kernel<<<ROWS / 8, 256>>>(qvals, cr,
                                    w00_l2_W, w00_l2_b,
                                    w2_l2_W, w2_l2_b,
                                    b2_l2_W, b2_l2_b,
                                    out);
}

// round 11
// speedup vs baseline: 2.5757x; 1.1849x over previous
#include <cuda_runtime.h>
#include <cuda_fp16.h>
#include <math.h>
#include <stdint.h>

// Problem dims
#define Bdim 128
#define Tdim 64
#define NAa  10
#define NVv  16
#define Kk   4
#define SDd  512
#define Hh   256
#define Ee   32
#define ROWS (Bdim * Tdim)        // 8192
#define NCAT 844                  // real concat width
#define NCATP 896                 // padded to 14*64
#define N2   544                  // (NV+1)*E
#define N2P  576                  // padded to 9*64

// ---------------- scratch (__device__ globals; no cudaMalloc) ----------------
__device__ float g_H1[(size_t)ROWS * NCAT];          // GEMM1 out (fp32)
__device__ float g_W1F[(size_t)ROWS * N2];           // GEMM2 out (fp32)
__device__ __align__(16) __half g_SThi[(size_t)ROWS * SDd];
__device__ __align__(16) __half g_STlo[(size_t)ROWS * SDd];
__device__ __align__(16) __half g_MIDhi[(size_t)ROWS * Hh];
__device__ __align__(16) __half g_MIDlo[(size_t)ROWS * Hh];
__device__ __align__(16) __half g_BT [(size_t)NCATP * SDd];   // B^T GEMM1 [c][k], single fp16
__device__ __align__(16) __half g_B2T[(size_t)N2P * Hh];      // B^T GEMM2, single fp16
__device__ float g_biascat[NCATP];
__device__ float g_bias2[N2P];
__device__ float g_hdelta[Hh];
__device__ float g_gdelta[1];

// ---------------- helpers ----------------
__device__ __forceinline__ uint32_t smem_u32(const void* p) {
    uint32_t a;
    asm("{ .reg .u64 t; cvta.to.shared.u64 t, %1; cvt.u32.u64 %0, t; }" : "=r"(a) : "l"(p));
    return a;
}
__device__ __forceinline__ void ldsm_x4(uint32_t* r, uint32_t addr) {
    asm volatile("ldmatrix.sync.aligned.m8n8.x4.shared.b16 {%0,%1,%2,%3}, [%4];"
                 : "=r"(r[0]), "=r"(r[1]), "=r"(r[2]), "=r"(r[3]) : "r"(addr));
}
__device__ __forceinline__ void mma_f16(float* c, const uint32_t* a, const uint32_t* b) {
    asm volatile("mma.sync.aligned.m16n8k16.row.col.f32.f16.f16.f32 "
                 "{%0,%1,%2,%3}, {%4,%5,%6,%7}, {%8,%9}, {%0,%1,%2,%3};"
                 : "+f"(c[0]), "+f"(c[1]), "+f"(c[2]), "+f"(c[3])
                 : "r"(a[0]), "r"(a[1]), "r"(a[2]), "r"(a[3]), "r"(b[0]), "r"(b[1]));
}
#define CP_ASYNC16(dst, src) \
    asm volatile("cp.async.cg.shared.global [%0], [%1], 16;" :: "r"(dst), "l"(src))
#define CP_COMMIT() asm volatile("cp.async.commit_group;" ::: "memory")
#define CP_WAIT(n)  asm volatile("cp.async.wait_group %0;" :: "n"(n) : "memory")

__device__ __forceinline__ uint32_t pack_half2(float a, float b) {
    __half h0 = __float2half(a), h1 = __float2half(b);
    return (uint32_t)__half_as_ushort(h0) | ((uint32_t)__half_as_ushort(h1) << 16);
}

// ---------------- split states into fp16 hi/lo ----------------
__global__ void split_states(const float* __restrict__ s) {
    int i = blockIdx.x * blockDim.x + threadIdx.x;     // over ROWS*SDd/4
    if (i >= ROWS * SDd / 4) return;
    float4 v = ((const float4*)s)[i];
    __half h0 = __float2half(v.x), h1 = __float2half(v.y);
    __half h2 = __float2half(v.z), h3 = __float2half(v.w);
    float r0 = v.x - __half2float(h0), r1 = v.y - __half2float(h1);
    float r2 = v.z - __half2float(h2), r3 = v.w - __half2float(h3);
    uint32_t hA = (uint32_t)__half_as_ushort(h0) | ((uint32_t)__half_as_ushort(h1) << 16);
    uint32_t hB = (uint32_t)__half_as_ushort(h2) | ((uint32_t)__half_as_ushort(h3) << 16);
    ((uint2*)g_SThi)[i] = make_uint2(hA, hB);
    ((uint2*)g_STlo)[i] = make_uint2(pack_half2(r0, r1), pack_half2(r2, r3));
}

// ---------------- pack transposed fp16 weights (+ fused deltas) ----------------
__global__ void pack1_kernel(
    const float* __restrict__ w00_l1_W, const float* __restrict__ w00_l1_b,
    const float* __restrict__ w1_l1_W,  const float* __restrict__ w1_l1_b,
    const float* __restrict__ w2_l1_W,  const float* __restrict__ w2_l1_b,
    const float* __restrict__ w01_W,    const float* __restrict__ w01_b,
    const float* __restrict__ b01_W,    const float* __restrict__ b01_b,
    const float* __restrict__ b00_W,    const float* __restrict__ b00_b,
    const float* __restrict__ b1_W,     const float* __restrict__ b1_b,
    const float* __restrict__ b2_l1_W,  const float* __restrict__ b2_l1_b)
{
    int idx = blockIdx.x * blockDim.x + threadIdx.x;   // over NCATP*SDd
    if (idx < NCATP * SDd) {
        int c = idx / SDd;
        int k = idx - c * SDd;
        float v = 0.f;
        if (c < NCAT) {
            if      (c < 256) v = w00_l1_W[k * 256 + c];
            else if (c < 512) v = w1_l1_W[k * 256 + (c - 256)];
            else if (c < 768) v = w2_l1_W[k * 256 + (c - 512)];
            else if (c < 778) v = w01_W[k * 10 + (c - 768)];
            else if (c == 778) v = b01_W[k];
            else if (c == 779) v = b00_W[k];
            else if (c < 812) v = b1_W[k * 32 + (c - 780)];
            else              v = b2_l1_W[k * 32 + (c - 812)];
        }
        g_BT[idx] = __float2half(v);
    }
    if (idx < NCATP) {
        int c = idx;
        float v = 0.f;
        if (c < NCAT) {
            if      (c < 256) v = w00_l1_b[c];
            else if (c < 512) v = w1_l1_b[c - 256];
            else if (c < 768) v = w2_l1_b[c - 512];
            else if (c < 778) v = w01_b[c - 768];
            else if (c == 778) v = b01_b[0];
            else if (c == 779) v = b00_b[0];
            else if (c < 812) v = b1_b[c - 780];
            else              v = b2_l1_b[c - 812];
        }
        g_biascat[c] = v;
    }
    // fused "all-ones onehot row" deltas
    if (idx < Hh) {
        float s = 0.f;
        #pragma unroll
        for (int j = 0; j < NVv; j++) s += w00_l1_W[(SDd + j) * 256 + idx];
        g_hdelta[idx] = s;
    }
    if (idx == Hh) {
        float s = 0.f;
        #pragma unroll
        for (int j = 0; j < NVv; j++) s += b00_W[SDd + j];
        g_gdelta[0] = s;
    }
}

__global__ void pack2_kernel(const float* __restrict__ w1_l2_W, const float* __restrict__ w1_l2_b)
{
    int idx = blockIdx.x * blockDim.x + threadIdx.x;   // over N2P*Hh
    if (idx < N2P * Hh) {
        int c = idx / Hh;
        int k = idx - c * Hh;
        float v = (c < N2) ? w1_l2_W[k * N2 + c] : 0.f;
        g_B2T[idx] = __float2half(v);
    }
    if (idx < N2P) g_bias2[idx] = (idx < N2) ? w1_l2_b[idx] : 0.f;
}

// ---------------------------------------------------------------------------
// mma.sync fp16 GEMM, 2-term split (A = Ah + Al, B single fp16), 2-stage
// cp.async pipeline. C[128 x 64 tile] = (Ah+Al) @ B^T.
// 256 threads, 8 warps (4M x 2N), warp tile 32x32 (2x4 m16n8k16).
// SMEM rows: 64 fp16 + 16B pad = 144 bytes (conflict-free ldmatrix).
// WRITE_MID: cols [256,512) -> relu + fp16 hi/lo split to g_MID*.
// ---------------------------------------------------------------------------
#define SROW    144
#define OF_AHI  0
#define OF_ALO  (128 * SROW)            // 18432
#define OF_B    (2 * 128 * SROW)        // 36864
#define STAGE   (OF_B + 64 * SROW)      // 46080
#define SMTOT   (2 * STAGE)             // 92160

template <bool WRITE_MID>
__global__ void __launch_bounds__(256)
gemm_mma(const __half* __restrict__ Ahi, const __half* __restrict__ Alo, int lda,
         const __half* __restrict__ B,
         const float* __restrict__ bias,
         float* __restrict__ C, int ldc, int Nvalid, int K)
{
    extern __shared__ char smem[];
    const uint32_t sb = smem_u32(smem);
    const int tid  = threadIdx.x;
    const int w    = tid >> 5;
    const int lane = tid & 31;
    const int wm   = w & 3;
    const int wn   = w >> 2;
    const int bm   = blockIdx.y * 128;
    const int bn   = blockIdx.x * 64;

    float acc[2][4][4];
    #pragma unroll
    for (int mt = 0; mt < 2; mt++)
        #pragma unroll
        for (int nt = 0; nt < 4; nt++)
            #pragma unroll
            for (int i = 0; i < 4; i++) acc[mt][nt][i] = 0.f;

    const int nch = K >> 6;
    const int arow = tid >> 3, asec = tid & 7;

    #define ISSUE_LOADS(c_, s_) do {                                             \
        const int k0_ = (c_) << 6;                                               \
        const uint32_t base_ = sb + (s_) * STAGE;                                \
        _Pragma("unroll")                                                        \
        for (int i = 0; i < 4; i++) {                                            \
            int row_ = arow + i * 32;                                            \
            uint32_t so_ = base_ + row_ * SROW + asec * 16;                      \
            const size_t go_ = (size_t)(bm + row_) * lda + k0_ + asec * 8;       \
            CP_ASYNC16(so_ + OF_AHI, (const char*)(Ahi + go_));                  \
            CP_ASYNC16(so_ + OF_ALO, (const char*)(Alo + go_));                  \
        }                                                                        \
        _Pragma("unroll")                                                        \
        for (int i = 0; i < 2; i++) {                                            \
            int row_ = arow + i * 32;                                            \
            uint32_t so_ = base_ + row_ * SROW + asec * 16;                      \
            const size_t go_ = (size_t)(bn + row_) * K + k0_ + asec * 8;         \
            CP_ASYNC16(so_ + OF_B, (const char*)(B + go_));                      \
        }                                                                        \
        CP_COMMIT();                                                             \
    } while (0)

    ISSUE_LOADS(0, 0);

    for (int c = 0; c < nch; c++) {
        if (c + 1 < nch) { ISSUE_LOADS(c + 1, (c + 1) & 1); CP_WAIT(1); }
        else             { CP_WAIT(0); }
        __syncthreads();

        const uint32_t stb = sb + (c & 1) * STAGE;
        #pragma unroll
        for (int ks = 0; ks < 4; ks++) {
            uint32_t ah[2][4], al[2][4];
            #pragma unroll
            for (int mt = 0; mt < 2; mt++) {
                int ar = wm * 32 + mt * 16 + (lane & 15);
                int ak = ks * 16 + (lane >> 4) * 8;
                uint32_t off = (uint32_t)(ar * SROW + ak * 2);
                ldsm_x4(ah[mt], stb + OF_AHI + off);
                ldsm_x4(al[mt], stb + OF_ALO + off);
            }
            uint32_t bh[4][2];
            #pragma unroll
            for (int jp = 0; jp < 2; jp++) {
                int tilei = lane >> 3, rin = lane & 7;
                int nrow = wn * 32 + jp * 16 + (tilei >> 1) * 8 + rin;
                int kof  = ks * 16 + (tilei & 1) * 8;
                uint32_t off = (uint32_t)(nrow * SROW + kof * 2);
                uint32_t r[4];
                ldsm_x4(r, stb + OF_B + off);
                bh[jp*2][0] = r[0]; bh[jp*2][1] = r[1];
                bh[jp*2+1][0] = r[2]; bh[jp*2+1][1] = r[3];
            }
            #pragma unroll
            for (int mt = 0; mt < 2; mt++)
                #pragma unroll
                for (int nt = 0; nt < 4; nt++) {
                    mma_f16(acc[mt][nt], ah[mt], bh[nt]);
                    mma_f16(acc[mt][nt], al[mt], bh[nt]);
                }
        }
        __syncthreads();
    }

    // Epilogue
    const int trow  = lane >> 2;
    const int tcol2 = (lane & 3) * 2;
    #pragma unroll
    for (int mt = 0; mt < 2; mt++) {
        #pragma unroll
        for (int nt = 0; nt < 4; nt++) {
            int col = bn + wn * 32 + nt * 8 + tcol2;
            float bv0 = bias[col], bv1 = bias[col + 1];
            #pragma unroll
            for (int half = 0; half < 2; half++) {
                int row = bm + wm * 32 + mt * 16 + trow + half * 8;
                float v0 = acc[mt][nt][half * 2 + 0] + bv0;
                float v1 = acc[mt][nt][half * 2 + 1] + bv1;
                bool is_mid = WRITE_MID && col >= 256 && col < 512;
                if (is_mid) {
                    float r0 = fmaxf(v0, 0.f), r1 = fmaxf(v1, 0.f);
                    __half h0 = __float2half(r0), h1 = __float2half(r1);
                    uint32_t ph = (uint32_t)__half_as_ushort(h0) | ((uint32_t)__half_as_ushort(h1) << 16);
                    uint32_t pl = pack_half2(r0 - __half2float(h0), r1 - __half2float(h1));
                    size_t mo = ((size_t)row * Hh + (col - 256)) >> 1;
                    ((uint32_t*)g_MIDhi)[mo] = ph;
                    ((uint32_t*)g_MIDlo)[mo] = pl;
                } else if (col < Nvalid) {
                    *(float2*)(C + (size_t)row * ldc + col) = make_float2(v0, v1);
                }
            }
        }
    }
}

// ---------------------------------------------------------------------------
// Final fused kernel: one warp per row; w2_l2_W staged in SMEM per block.
// ---------------------------------------------------------------------------
__global__ void __launch_bounds__(256)
final_kernel(const float* __restrict__ qvals,
             const int*   __restrict__ cr,
             const float* __restrict__ w00_l2_W,  // (256,4)
             const float* __restrict__ w00_l2_b,  // (4)
             const float* __restrict__ w2_l2_W,   // (256,32)
             const float* __restrict__ w2_l2_b,   // (32)
             const float* __restrict__ b2_l2_W,   // (32,1)
             const float* __restrict__ b2_l2_b,   // (1)
             float* __restrict__ out)
{
    __shared__ float s_a2[8][Hh];
    __shared__ float s_q[8][NAa];
    __shared__ float s_w2[Hh * Ee];   // 32 KB

    const int w = threadIdx.x >> 5;
    const int l = threadIdx.x & 31;
    const int r = blockIdx.x * 8 + w;
    const int b = r >> 6;                 // batch index (T = 64)
    const float* __restrict__ row = g_H1 + (size_t)r * NCAT;

    #pragma unroll
    for (int i = 0; i < 8; i++)
        ((float4*)s_w2)[i * 256 + threadIdx.x] = ((const float4*)w2_l2_W)[i * 256 + threadIdx.x];

    for (int i = l; i < Hh; i += 32)
        s_a2[w][i] = fmaxf(row[512 + i], 0.f);
    if (l < NAa) s_q[w][l] = qvals[r * NAa + l];
    __syncthreads();

    const bool mod = (b < NVv);

    float acc0[4] = {0.f, 0.f, 0.f, 0.f};
    float accm[4] = {0.f, 0.f, 0.f, 0.f};
    for (int kk = l; kk < Hh; kk += 32) {
        float hb = row[kk];
        float h  = fmaxf(hb, 0.f);
        float hm = fmaxf(hb + g_hdelta[kk], 0.f);
        float4 wv = *(const float4*)(w00_l2_W + kk * 4);
        acc0[0] += h  * wv.x; acc0[1] += h  * wv.y; acc0[2] += h  * wv.z; acc0[3] += h  * wv.w;
        accm[0] += hm * wv.x; accm[1] += hm * wv.y; accm[2] += hm * wv.z; accm[3] += hm * wv.w;
    }
    #pragma unroll
    for (int o = 0; o < 4; o++) {
        #pragma unroll
        for (int off = 16; off; off >>= 1) {
            acc0[o] += __shfl_xor_sync(0xffffffffu, acc0[o], off);
            accm[o] += __shfl_xor_sync(0xffffffffu, accm[o], off);
        }
    }
    float w0c[4], w0m[4];
    #pragma unroll
    for (int o = 0; o < 4; o++) {
        w0c[o] = fabsf(acc0[o] + w00_l2_b[o]);
        w0m[o] = fabsf(accm[o] + w00_l2_b[o]);
    }

    float acc2 = 0.f;
    #pragma unroll 8
    for (int kk = 0; kk < Hh; kk++) acc2 += s_a2[w][kk] * s_w2[kk * Ee + l];
    float w2a = fabsf(acc2 + w2_l2_b[l]);

    float xb2 = fmaxf(row[812 + l], 0.f) * b2_l2_W[l];
    #pragma unroll
    for (int off = 16; off; off >>= 1) xb2 += __shfl_xor_sync(0xffffffffu, xb2, off);
    float b2 = xb2 + b2_l2_b[0];

    float b1v = row[780 + l];

    float gq_l;
    if (l < NVv) {
        const int* __restrict__ crr = cr + (size_t)r * (Kk * NVv);
        float g = 0.f;
        #pragma unroll
        for (int k = 0; k < Kk; k++) {
            int idx = crr[k * NVv + l];
            float wk = (mod && l == b) ? w0m[k] : w0c[k];
            g += s_q[w][idx] * wk;
        }
        g += row[779];
        if (mod && l == b) g += g_gdelta[0];
        gq_l = g;
    } else {
        float oth = row[778];
        #pragma unroll
        for (int a = 0; a < NAa; a++) oth += s_q[w][a] * row[768 + a];
        gq_l = oth;
    }

    const float* __restrict__ w1r = g_W1F + (size_t)r * N2;
    float accH = b1v;
    #pragma unroll
    for (int v = 0; v <= NVv; v++) {
        float gqv = __shfl_sync(0xffffffffu, gq_l, v);
        accH += gqv * fabsf(w1r[v * Ee + l]);
    }
    float hidden = (accH > 0.f) ? accH : expm1f(accH);

    float part = hidden * w2a;
    #pragma unroll
    for (int off = 16; off; off >>= 1) part += __shfl_xor_sync(0xffffffffu, part, off);
    if (l == 0) out[r] = part + b2;
}

// ---------------------------------------------------------------------------
extern "C" void kernel_launch(void* const* d_in, const int* in_sizes, int n_in,
                              void* d_out, int out_size)
{
    const float* qvals    = (const float*)d_in[0];
    const int*   cr       = (const int*)  d_in[1];
    const float* states   = (const float*)d_in[2];
    const float* w00_l1_W = (const float*)d_in[3];
    const float* w00_l1_b = (const float*)d_in[4];
    const float* w00_l2_W = (const float*)d_in[5];
    const float* w00_l2_b = (const float*)d_in[6];
    const float* b00_W    = (const float*)d_in[7];
    const float* b00_b    = (const float*)d_in[8];
    const float* w01_W    = (const float*)d_in[9];
    const float* w01_b    = (const float*)d_in[10];
    const float* b01_W    = (const float*)d_in[11];
    const float* b01_b    = (const float*)d_in[12];
    const float* w1_l1_W  = (const float*)d_in[13];
    const float* w1_l1_b  = (const float*)d_in[14];
    const float* w1_l2_W  = (const float*)d_in[15];
    const float* w1_l2_b  = (const float*)d_in[16];
    const float* b1_W     = (const float*)d_in[17];
    const float* b1_b     = (const float*)d_in[18];
    const float* w2_l1_W  = (const float*)d_in[19];
    const float* w2_l1_b  = (const float*)d_in[20];
    const float* w2_l2_W  = (const float*)d_in[21];
    const float* w2_l2_b  = (const float*)d_in[22];
    const float* b2_l1_W  = (const float*)d_in[23];
    const float* b2_l1_b  = (const float*)d_in[24];
    const float* b2_l2_W  = (const float*)d_in[25];
    const float* b2_l2_b  = (const float*)d_in[26];
    float* out = (float*)d_out;

    static int attr_done = 0;
    if (!attr_done) {
        cudaFuncSetAttribute(gemm_mma<true>,  cudaFuncAttributeMaxDynamicSharedMemorySize, SMTOT);
        cudaFuncSetAttribute(gemm_mma<false>, cudaFuncAttributeMaxDynamicSharedMemorySize, SMTOT);
        attr_done = 1;
    }

    float *H1, *W1F, *biascat, *bias2;
    __half *SThi, *STlo, *MIDhi, *MIDlo, *BT, *B2T;
    cudaGetSymbolAddress((void**)&H1,      g_H1);
    cudaGetSymbolAddress((void**)&W1F,     g_W1F);
    cudaGetSymbolAddress((void**)&biascat, g_biascat);
    cudaGetSymbolAddress((void**)&bias2,   g_bias2);
    cudaGetSymbolAddress((void**)&SThi,    g_SThi);
    cudaGetSymbolAddress((void**)&STlo,    g_STlo);
    cudaGetSymbolAddress((void**)&MIDhi,   g_MIDhi);
    cudaGetSymbolAddress((void**)&MIDlo,   g_MIDlo);
    cudaGetSymbolAddress((void**)&BT,      g_BT);
    cudaGetSymbolAddress((void**)&B2T,     g_B2T);

    // 1) precompute: fp16 splits + transposed packed weights (+deltas fused)
    split_states<<<(ROWS * SDd / 4 + 255) / 256, 256>>>(states);
    pack1_kernel<<<(NCATP * SDd + 255) / 256, 256>>>(
        w00_l1_W, w00_l1_b, w1_l1_W, w1_l1_b, w2_l1_W, w2_l1_b,
        w01_W, w01_b, b01_W, b01_b, b00_W, b00_b, b1_W, b1_b, b2_l1_W, b2_l1_b);
    pack2_kernel<<<(N2P * Hh + 255) / 256, 256>>>(w1_l2_W, w1_l2_b);

    // 2) GEMM1 (mma.sync fp16 2-term, cp.async pipelined)
    {
        dim3 grid(NCATP / 64, ROWS / 128);
        gemm_mma<true><<<grid, 256, SMTOT>>>(SThi, STlo, SDd, BT,
                                             biascat, H1, NCAT, NCAT, SDd);
    }

    // 3) GEMM2
    {
        dim3 grid(N2P / 64, ROWS / 128);
        gemm_mma<false><<<grid, 256, SMTOT>>>(MIDhi, MIDlo, Hh, B2T,
                                              bias2, W1F, N2, N2, Hh);
    }

    // 4) fused epilogue
    final_kernel<<<ROWS / 8, 256>>>(qvals, cr,
                                    w00_l2_W, w00_l2_b,
                                    w2_l2_W, w2_l2_b,
                                    b2_l2_W, b2_l2_b,
                                    out);
}

// round 12
// speedup vs baseline: 3.5066x; 1.3614x over previous
#include <cuda_runtime.h>
#include <cuda_fp16.h>
#include <math.h>
#include <stdint.h>

// Problem dims
#define Bdim 128
#define Tdim 64
#define NAa  10
#define NVv  16
#define Kk   4
#define SDd  512
#define Hh   256
#define Ee   32
#define ROWS (Bdim * Tdim)        // 8192
#define NCAT 844                  // real concat width
#define NCATP 896                 // padded to 14*64
#define N2   544                  // (NV+1)*E
#define N2P  576                  // padded to 9*64

// ---------------- scratch (__device__ globals; no cudaMalloc) ----------------
__device__ float g_H1[(size_t)ROWS * NCAT];          // GEMM1 out (fp32)
__device__ float g_W1F[(size_t)ROWS * N2];           // GEMM2 out (fp32)
__device__ __align__(16) __half g_ST [(size_t)ROWS * SDd];    // states fp16
__device__ __align__(16) __half g_MID[(size_t)ROWS * Hh];     // relu(H1 mid) fp16
__device__ __align__(16) __half g_BT [(size_t)NCATP * SDd];   // B^T GEMM1 [c][k]
__device__ __align__(16) __half g_B2T[(size_t)N2P * Hh];      // B^T GEMM2
__device__ float g_biascat[NCATP];
__device__ float g_bias2[N2P];
__device__ float g_hdelta[Hh];
__device__ float g_gdelta[1];

// ---------------- helpers ----------------
__device__ __forceinline__ uint32_t smem_u32(const void* p) {
    uint32_t a;
    asm("{ .reg .u64 t; cvta.to.shared.u64 t, %1; cvt.u32.u64 %0, t; }" : "=r"(a) : "l"(p));
    return a;
}
__device__ __forceinline__ void ldsm_x4(uint32_t* r, uint32_t addr) {
    asm volatile("ldmatrix.sync.aligned.m8n8.x4.shared.b16 {%0,%1,%2,%3}, [%4];"
                 : "=r"(r[0]), "=r"(r[1]), "=r"(r[2]), "=r"(r[3]) : "r"(addr));
}
__device__ __forceinline__ void mma_f16(float* c, const uint32_t* a, const uint32_t* b) {
    asm volatile("mma.sync.aligned.m16n8k16.row.col.f32.f16.f16.f32 "
                 "{%0,%1,%2,%3}, {%4,%5,%6,%7}, {%8,%9}, {%0,%1,%2,%3};"
                 : "+f"(c[0]), "+f"(c[1]), "+f"(c[2]), "+f"(c[3])
                 : "r"(a[0]), "r"(a[1]), "r"(a[2]), "r"(a[3]), "r"(b[0]), "r"(b[1]));
}
#define CP_ASYNC16(dst, src) \
    asm volatile("cp.async.cg.shared.global [%0], [%1], 16;" :: "r"(dst), "l"(src))
#define CP_COMMIT() asm volatile("cp.async.commit_group;" ::: "memory")
#define CP_WAIT(n)  asm volatile("cp.async.wait_group %0;" :: "n"(n) : "memory")

// ---------------- convert states to fp16 ----------------
__global__ void split_states(const float* __restrict__ s) {
    int i = blockIdx.x * blockDim.x + threadIdx.x;     // over ROWS*SDd/4
    if (i >= ROWS * SDd / 4) return;
    float4 v = ((const float4*)s)[i];
    __half h0 = __float2half(v.x), h1 = __float2half(v.y);
    __half h2 = __float2half(v.z), h3 = __float2half(v.w);
    uint32_t hA = (uint32_t)__half_as_ushort(h0) | ((uint32_t)__half_as_ushort(h1) << 16);
    uint32_t hB = (uint32_t)__half_as_ushort(h2) | ((uint32_t)__half_as_ushort(h3) << 16);
    ((uint2*)g_ST)[i] = make_uint2(hA, hB);
}

// ---------------- pack transposed fp16 weights (+ fused deltas) ----------------
__global__ void pack1_kernel(
    const float* __restrict__ w00_l1_W, const float* __restrict__ w00_l1_b,
    const float* __restrict__ w1_l1_W,  const float* __restrict__ w1_l1_b,
    const float* __restrict__ w2_l1_W,  const float* __restrict__ w2_l1_b,
    const float* __restrict__ w01_W,    const float* __restrict__ w01_b,
    const float* __restrict__ b01_W,    const float* __restrict__ b01_b,
    const float* __restrict__ b00_W,    const float* __restrict__ b00_b,
    const float* __restrict__ b1_W,     const float* __restrict__ b1_b,
    const float* __restrict__ b2_l1_W,  const float* __restrict__ b2_l1_b)
{
    int idx = blockIdx.x * blockDim.x + threadIdx.x;   // over NCATP*SDd
    if (idx < NCATP * SDd) {
        int c = idx / SDd;
        int k = idx - c * SDd;
        float v = 0.f;
        if (c < NCAT) {
            if      (c < 256) v = w00_l1_W[k * 256 + c];
            else if (c < 512) v = w1_l1_W[k * 256 + (c - 256)];
            else if (c < 768) v = w2_l1_W[k * 256 + (c - 512)];
            else if (c < 778) v = w01_W[k * 10 + (c - 768)];
            else if (c == 778) v = b01_W[k];
            else if (c == 779) v = b00_W[k];
            else if (c < 812) v = b1_W[k * 32 + (c - 780)];
            else              v = b2_l1_W[k * 32 + (c - 812)];
        }
        g_BT[idx] = __float2half(v);
    }
    if (idx < NCATP) {
        int c = idx;
        float v = 0.f;
        if (c < NCAT) {
            if      (c < 256) v = w00_l1_b[c];
            else if (c < 512) v = w1_l1_b[c - 256];
            else if (c < 768) v = w2_l1_b[c - 512];
            else if (c < 778) v = w01_b[c - 768];
            else if (c == 778) v = b01_b[0];
            else if (c == 779) v = b00_b[0];
            else if (c < 812) v = b1_b[c - 780];
            else              v = b2_l1_b[c - 812];
        }
        g_biascat[c] = v;
    }
    // fused "all-ones onehot row" deltas
    if (idx < Hh) {
        float s = 0.f;
        #pragma unroll
        for (int j = 0; j < NVv; j++) s += w00_l1_W[(SDd + j) * 256 + idx];
        g_hdelta[idx] = s;
    }
    if (idx == Hh) {
        float s = 0.f;
        #pragma unroll
        for (int j = 0; j < NVv; j++) s += b00_W[SDd + j];
        g_gdelta[0] = s;
    }
}

__global__ void pack2_kernel(const float* __restrict__ w1_l2_W, const float* __restrict__ w1_l2_b)
{
    int idx = blockIdx.x * blockDim.x + threadIdx.x;   // over N2P*Hh
    if (idx < N2P * Hh) {
        int c = idx / Hh;
        int k = idx - c * Hh;
        float v = (c < N2) ? w1_l2_W[k * N2 + c] : 0.f;
        g_B2T[idx] = __float2half(v);
    }
    if (idx < N2P) g_bias2[idx] = (idx < N2) ? w1_l2_b[idx] : 0.f;
}

// ---------------------------------------------------------------------------
// mma.sync fp16 GEMM (single term), 2-stage cp.async pipeline.
// C[128 x 64 tile] = A @ B^T, fp32 accum.
// 256 threads, 8 warps (4M x 2N), warp tile 32x32 (2x4 m16n8k16).
// SMEM rows: 64 fp16 + 16B pad = 144 bytes (conflict-free ldmatrix).
// WRITE_MID: cols [256,512) -> relu + fp16 to g_MID (fp32 store skipped).
// ---------------------------------------------------------------------------
#define SROW    144
#define OF_A    0
#define OF_B    (128 * SROW)            // 18432
#define STAGE   (OF_B + 64 * SROW)      // 27648
#define SMTOT   (2 * STAGE)             // 55296

template <bool WRITE_MID>
__global__ void __launch_bounds__(256)
gemm_mma(const __half* __restrict__ A, int lda,
         const __half* __restrict__ B,
         const float* __restrict__ bias,
         float* __restrict__ C, int ldc, int Nvalid, int K)
{
    extern __shared__ char smem[];
    const uint32_t sb = smem_u32(smem);
    const int tid  = threadIdx.x;
    const int w    = tid >> 5;
    const int lane = tid & 31;
    const int wm   = w & 3;
    const int wn   = w >> 2;
    const int bm   = blockIdx.y * 128;
    const int bn   = blockIdx.x * 64;

    float acc[2][4][4];
    #pragma unroll
    for (int mt = 0; mt < 2; mt++)
        #pragma unroll
        for (int nt = 0; nt < 4; nt++)
            #pragma unroll
            for (int i = 0; i < 4; i++) acc[mt][nt][i] = 0.f;

    const int nch = K >> 6;
    const int arow = tid >> 3, asec = tid & 7;

    #define ISSUE_LOADS(c_, s_) do {                                             \
        const int k0_ = (c_) << 6;                                               \
        const uint32_t base_ = sb + (s_) * STAGE;                                \
        _Pragma("unroll")                                                        \
        for (int i = 0; i < 4; i++) {                                            \
            int row_ = arow + i * 32;                                            \
            uint32_t so_ = base_ + row_ * SROW + asec * 16;                      \
            const size_t go_ = (size_t)(bm + row_) * lda + k0_ + asec * 8;       \
            CP_ASYNC16(so_ + OF_A, (const char*)(A + go_));                      \
        }                                                                        \
        _Pragma("unroll")                                                        \
        for (int i = 0; i < 2; i++) {                                            \
            int row_ = arow + i * 32;                                            \
            uint32_t so_ = base_ + row_ * SROW + asec * 16;                      \
            const size_t go_ = (size_t)(bn + row_) * K + k0_ + asec * 8;         \
            CP_ASYNC16(so_ + OF_B, (const char*)(B + go_));                      \
        }                                                                        \
        CP_COMMIT();                                                             \
    } while (0)

    ISSUE_LOADS(0, 0);

    for (int c = 0; c < nch; c++) {
        if (c + 1 < nch) { ISSUE_LOADS(c + 1, (c + 1) & 1); CP_WAIT(1); }
        else             { CP_WAIT(0); }
        __syncthreads();

        const uint32_t stb = sb + (c & 1) * STAGE;
        #pragma unroll
        for (int ks = 0; ks < 4; ks++) {
            uint32_t ah[2][4];
            #pragma unroll
            for (int mt = 0; mt < 2; mt++) {
                int ar = wm * 32 + mt * 16 + (lane & 15);
                int ak = ks * 16 + (lane >> 4) * 8;
                ldsm_x4(ah[mt], stb + OF_A + (uint32_t)(ar * SROW + ak * 2));
            }
            uint32_t bh[4][2];
            #pragma unroll
            for (int jp = 0; jp < 2; jp++) {
                int tilei = lane >> 3, rin = lane & 7;
                int nrow = wn * 32 + jp * 16 + (tilei >> 1) * 8 + rin;
                int kof  = ks * 16 + (tilei & 1) * 8;
                uint32_t r[4];
                ldsm_x4(r, stb + OF_B + (uint32_t)(nrow * SROW + kof * 2));
                bh[jp*2][0] = r[0]; bh[jp*2][1] = r[1];
                bh[jp*2+1][0] = r[2]; bh[jp*2+1][1] = r[3];
            }
            #pragma unroll
            for (int mt = 0; mt < 2; mt++)
                #pragma unroll
                for (int nt = 0; nt < 4; nt++)
                    mma_f16(acc[mt][nt], ah[mt], bh[nt]);
        }
        __syncthreads();
    }

    // Epilogue
    const int trow  = lane >> 2;
    const int tcol2 = (lane & 3) * 2;
    #pragma unroll
    for (int mt = 0; mt < 2; mt++) {
        #pragma unroll
        for (int nt = 0; nt < 4; nt++) {
            int col = bn + wn * 32 + nt * 8 + tcol2;
            float bv0 = bias[col], bv1 = bias[col + 1];
            #pragma unroll
            for (int half = 0; half < 2; half++) {
                int row = bm + wm * 32 + mt * 16 + trow + half * 8;
                float v0 = acc[mt][nt][half * 2 + 0] + bv0;
                float v1 = acc[mt][nt][half * 2 + 1] + bv1;
                bool is_mid = WRITE_MID && col >= 256 && col < 512;
                if (is_mid) {
                    float r0 = fmaxf(v0, 0.f), r1 = fmaxf(v1, 0.f);
                    __half h0 = __float2half(r0), h1 = __float2half(r1);
                    uint32_t ph = (uint32_t)__half_as_ushort(h0) | ((uint32_t)__half_as_ushort(h1) << 16);
                    ((uint32_t*)g_MID)[((size_t)row * Hh + (col - 256)) >> 1] = ph;
                } else if (col < Nvalid) {
                    *(float2*)(C + (size_t)row * ldc + col) = make_float2(v0, v1);
                }
            }
        }
    }
}

// ---------------------------------------------------------------------------
// Final fused kernel: one warp per row; w2_l2_W staged in SMEM per block.
// ---------------------------------------------------------------------------
__global__ void __launch_bounds__(256)
final_kernel(const float* __restrict__ qvals,
             const int*   __restrict__ cr,
             const float* __restrict__ w00_l2_W,  // (256,4)
             const float* __restrict__ w00_l2_b,  // (4)
             const float* __restrict__ w2_l2_W,   // (256,32)
             const float* __restrict__ w2_l2_b,   // (32)
             const float* __restrict__ b2_l2_W,   // (32,1)
             const float* __restrict__ b2_l2_b,   // (1)
             float* __restrict__ out)
{
    __shared__ float s_a2[8][Hh];
    __shared__ float s_q[8][NAa];
    __shared__ float s_w2[Hh * Ee];   // 32 KB

    const int w = threadIdx.x >> 5;
    const int l = threadIdx.x & 31;
    const int r = blockIdx.x * 8 + w;
    const int b = r >> 6;                 // batch index (T = 64)
    const float* __restrict__ row = g_H1 + (size_t)r * NCAT;

    #pragma unroll
    for (int i = 0; i < 8; i++)
        ((float4*)s_w2)[i * 256 + threadIdx.x] = ((const float4*)w2_l2_W)[i * 256 + threadIdx.x];

    for (int i = l; i < Hh; i += 32)
        s_a2[w][i] = fmaxf(row[512 + i], 0.f);
    if (l < NAa) s_q[w][l] = qvals[r * NAa + l];
    __syncthreads();

    const bool mod = (b < NVv);

    float acc0[4] = {0.f, 0.f, 0.f, 0.f};
    float accm[4] = {0.f, 0.f, 0.f, 0.f};
    for (int kk = l; kk < Hh; kk += 32) {
        float hb = row[kk];
        float h  = fmaxf(hb, 0.f);
        float hm = fmaxf(hb + g_hdelta[kk], 0.f);
        float4 wv = *(const float4*)(w00_l2_W + kk * 4);
        acc0[0] += h  * wv.x; acc0[1] += h  * wv.y; acc0[2] += h  * wv.z; acc0[3] += h  * wv.w;
        accm[0] += hm * wv.x; accm[1] += hm * wv.y; accm[2] += hm * wv.z; accm[3] += hm * wv.w;
    }
    #pragma unroll
    for (int o = 0; o < 4; o++) {
        #pragma unroll
        for (int off = 16; off; off >>= 1) {
            acc0[o] += __shfl_xor_sync(0xffffffffu, acc0[o], off);
            accm[o] += __shfl_xor_sync(0xffffffffu, accm[o], off);
        }
    }
    float w0c[4], w0m[4];
    #pragma unroll
    for (int o = 0; o < 4; o++) {
        w0c[o] = fabsf(acc0[o] + w00_l2_b[o]);
        w0m[o] = fabsf(accm[o] + w00_l2_b[o]);
    }

    float acc2 = 0.f;
    #pragma unroll 8
    for (int kk = 0; kk < Hh; kk++) acc2 += s_a2[w][kk] * s_w2[kk * Ee + l];
    float w2a = fabsf(acc2 + w2_l2_b[l]);

    float xb2 = fmaxf(row[812 + l], 0.f) * b2_l2_W[l];
    #pragma unroll
    for (int off = 16; off; off >>= 1) xb2 += __shfl_xor_sync(0xffffffffu, xb2, off);
    float b2 = xb2 + b2_l2_b[0];

    float b1v = row[780 + l];

    float gq_l;
    if (l < NVv) {
        const int* __restrict__ crr = cr + (size_t)r * (Kk * NVv);
        float g = 0.f;
        #pragma unroll
        for (int k = 0; k < Kk; k++) {
            int idx = crr[k * NVv + l];
            float wk = (mod && l == b) ? w0m[k] : w0c[k];
            g += s_q[w][idx] * wk;
        }
        g += row[779];
        if (mod && l == b) g += g_gdelta[0];
        gq_l = g;
    } else {
        float oth = row[778];
        #pragma unroll
        for (int a = 0; a < NAa; a++) oth += s_q[w][a] * row[768 + a];
        gq_l = oth;
    }

    const float* __restrict__ w1r = g_W1F + (size_t)r * N2;
    float accH = b1v;
    #pragma unroll
    for (int v = 0; v <= NVv; v++) {
        float gqv = __shfl_sync(0xffffffffu, gq_l, v);
        accH += gqv * fabsf(w1r[v * Ee + l]);
    }
    float hidden = (accH > 0.f) ? accH : expm1f(accH);

    float part = hidden * w2a;
    #pragma unroll
    for (int off = 16; off; off >>= 1) part += __shfl_xor_sync(0xffffffffu, part, off);
    if (l == 0) out[r] = part + b2;
}

// ---------------------------------------------------------------------------
extern "C" void kernel_launch(void* const* d_in, const int* in_sizes, int n_in,
                              void* d_out, int out_size)
{
    const float* qvals    = (const float*)d_in[0];
    const int*   cr       = (const int*)  d_in[1];
    const float* states   = (const float*)d_in[2];
    const float* w00_l1_W = (const float*)d_in[3];
    const float* w00_l1_b = (const float*)d_in[4];
    const float* w00_l2_W = (const float*)d_in[5];
    const float* w00_l2_b = (const float*)d_in[6];
    const float* b00_W    = (const float*)d_in[7];
    const float* b00_b    = (const float*)d_in[8];
    const float* w01_W    = (const float*)d_in[9];
    const float* w01_b    = (const float*)d_in[10];
    const float* b01_W    = (const float*)d_in[11];
    const float* b01_b    = (const float*)d_in[12];
    const float* w1_l1_W  = (const float*)d_in[13];
    const float* w1_l1_b  = (const float*)d_in[14];
    const float* w1_l2_W  = (const float*)d_in[15];
    const float* w1_l2_b  = (const float*)d_in[16];
    const float* b1_W     = (const float*)d_in[17];
    const float* b1_b     = (const float*)d_in[18];
    const float* w2_l1_W  = (const float*)d_in[19];
    const float* w2_l1_b  = (const float*)d_in[20];
    const float* w2_l2_W  = (const float*)d_in[21];
    const float* w2_l2_b  = (const float*)d_in[22];
    const float* b2_l1_W  = (const float*)d_in[23];
    const float* b2_l1_b  = (const float*)d_in[24];
    const float* b2_l2_W  = (const float*)d_in[25];
    const float* b2_l2_b  = (const float*)d_in[26];
    float* out = (float*)d_out;

    static int attr_done = 0;
    if (!attr_done) {
        cudaFuncSetAttribute(gemm_mma<true>,  cudaFuncAttributeMaxDynamicSharedMemorySize, SMTOT);
        cudaFuncSetAttribute(gemm_mma<false>, cudaFuncAttributeMaxDynamicSharedMemorySize, SMTOT);
        attr_done = 1;
    }

    float *H1, *W1F, *biascat, *bias2;
    __half *ST, *MID, *BT, *B2T;
    cudaGetSymbolAddress((void**)&H1,      g_H1);
    cudaGetSymbolAddress((void**)&W1F,     g_W1F);
    cudaGetSymbolAddress((void**)&biascat, g_biascat);
    cudaGetSymbolAddress((void**)&bias2,   g_bias2);
    cudaGetSymbolAddress((void**)&ST,      g_ST);
    cudaGetSymbolAddress((void**)&MID,     g_MID);
    cudaGetSymbolAddress((void**)&BT,      g_BT);
    cudaGetSymbolAddress((void**)&B2T,     g_B2T);

    // 1) precompute: fp16 convert + transposed packed weights (+deltas fused)
    split_states<<<(ROWS * SDd / 4 + 255) / 256, 256>>>(states);
    pack1_kernel<<<(NCATP * SDd + 255) / 256, 256>>>(
        w00_l1_W, w00_l1_b, w1_l1_W, w1_l1_b, w2_l1_W, w2_l1_b,
        w01_W, w01_b, b01_W, b01_b, b00_W, b00_b, b1_W, b1_b, b2_l1_W, b2_l1_b);
    pack2_kernel<<<(N2P * Hh + 255) / 256, 256>>>(w1_l2_W, w1_l2_b);

    // 2) GEMM1 (mma.sync fp16 single-term, cp.async pipelined)
    {
        dim3 grid(NCATP / 64, ROWS / 128);
        gemm_mma<true><<<grid, 256, SMTOT>>>(ST, SDd, BT,
                                             biascat, H1, NCAT, NCAT, SDd);
    }

    // 3) GEMM2
    {
        dim3 grid(N2P / 64, ROWS / 128);
        gemm_mma<false><<<grid, 256, SMTOT>>>(MID, Hh, B2T,
                                              bias2, W1F, N2, N2, Hh);
    }

    // 4) fused epilogue
    final_kernel<<<ROWS / 8, 256>>>(qvals, cr,
                                    w00_l2_W, w00_l2_b,
                                    w2_l2_W, w2_l2_b,
                                    b2_l2_W, b2_l2_b,
                                    out);
}

// round 13
// speedup vs baseline: 4.1388x; 1.1803x over previous
#include <cuda_runtime.h>
#include <cuda_fp16.h>
#include <math.h>
#include <stdint.h>

// Problem dims
#define Bdim 128
#define Tdim 64
#define NAa  10
#define NVv  16
#define Kk   4
#define SDd  512
#define Hh   256
#define Ee   32
#define ROWS (Bdim * Tdim)        // 8192
#define NCAT 844                  // real concat width
#define NCATP 896                 // padded to 14*64
#define N2   544                  // (NV+1)*E
#define N2P  576                  // padded: 544 w1 cols + 32 w2 cols
#define MIDW 512                  // MID width: relu(H1[:,256:768])
#define K2   512                  // GEMM2 full K (block-diagonal)

// ---------------- scratch (__device__ globals; no cudaMalloc) ----------------
__device__ float g_H1[(size_t)ROWS * NCAT];           // GEMM1 out (fp32; mid cols skipped)
__device__ float g_W1F[(size_t)ROWS * N2P];           // GEMM2 out (fp32): w1 pre-abs | w2 pre-abs
__device__ __align__(16) __half g_ST [(size_t)ROWS * SDd];    // states fp16
__device__ __align__(16) __half g_MID[(size_t)ROWS * MIDW];   // relu(H1[:,256:768]) fp16
__device__ __align__(16) __half g_BT [(size_t)NCATP * SDd];   // B^T GEMM1 [c][k]
__device__ __align__(16) __half g_B2T[(size_t)N2P * K2];      // B^T GEMM2 block-diagonal
__device__ float g_biascat[NCATP];
__device__ float g_bias2[N2P];
__device__ float g_hdelta[Hh];
__device__ float g_gdelta[1];

// ---------------- helpers ----------------
__device__ __forceinline__ uint32_t smem_u32(const void* p) {
    uint32_t a;
    asm("{ .reg .u64 t; cvta.to.shared.u64 t, %1; cvt.u32.u64 %0, t; }" : "=r"(a) : "l"(p));
    return a;
}
__device__ __forceinline__ void ldsm_x4(uint32_t* r, uint32_t addr) {
    asm volatile("ldmatrix.sync.aligned.m8n8.x4.shared.b16 {%0,%1,%2,%3}, [%4];"
                 : "=r"(r[0]), "=r"(r[1]), "=r"(r[2]), "=r"(r[3]) : "r"(addr));
}
__device__ __forceinline__ void mma_f16(float* c, const uint32_t* a, const uint32_t* b) {
    asm volatile("mma.sync.aligned.m16n8k16.row.col.f32.f16.f16.f32 "
                 "{%0,%1,%2,%3}, {%4,%5,%6,%7}, {%8,%9}, {%0,%1,%2,%3};"
                 : "+f"(c[0]), "+f"(c[1]), "+f"(c[2]), "+f"(c[3])
                 : "r"(a[0]), "r"(a[1]), "r"(a[2]), "r"(a[3]), "r"(b[0]), "r"(b[1]));
}
#define CP_ASYNC16(dst, src) \
    asm volatile("cp.async.cg.shared.global [%0], [%1], 16;" :: "r"(dst), "l"(src))
#define CP_COMMIT() asm volatile("cp.async.commit_group;" ::: "memory")
#define CP_WAIT(n)  asm volatile("cp.async.wait_group %0;" :: "n"(n) : "memory")

// ---------------- convert states to fp16 ----------------
__global__ void split_states(const float* __restrict__ s) {
    int i = blockIdx.x * blockDim.x + threadIdx.x;     // over ROWS*SDd/4
    if (i >= ROWS * SDd / 4) return;
    float4 v = ((const float4*)s)[i];
    __half h0 = __float2half(v.x), h1 = __float2half(v.y);
    __half h2 = __float2half(v.z), h3 = __float2half(v.w);
    uint32_t hA = (uint32_t)__half_as_ushort(h0) | ((uint32_t)__half_as_ushort(h1) << 16);
    uint32_t hB = (uint32_t)__half_as_ushort(h2) | ((uint32_t)__half_as_ushort(h3) << 16);
    ((uint2*)g_ST)[i] = make_uint2(hA, hB);
}

// ---------------- pack transposed fp16 weights (+ fused deltas) ----------------
__global__ void pack1_kernel(
    const float* __restrict__ w00_l1_W, const float* __restrict__ w00_l1_b,
    const float* __restrict__ w1_l1_W,  const float* __restrict__ w1_l1_b,
    const float* __restrict__ w2_l1_W,  const float* __restrict__ w2_l1_b,
    const float* __restrict__ w01_W,    const float* __restrict__ w01_b,
    const float* __restrict__ b01_W,    const float* __restrict__ b01_b,
    const float* __restrict__ b00_W,    const float* __restrict__ b00_b,
    const float* __restrict__ b1_W,     const float* __restrict__ b1_b,
    const float* __restrict__ b2_l1_W,  const float* __restrict__ b2_l1_b)
{
    int idx = blockIdx.x * blockDim.x + threadIdx.x;   // over NCATP*SDd
    if (idx < NCATP * SDd) {
        int c = idx / SDd;
        int k = idx - c * SDd;
        float v = 0.f;
        if (c < NCAT) {
            if      (c < 256) v = w00_l1_W[k * 256 + c];
            else if (c < 512) v = w1_l1_W[k * 256 + (c - 256)];
            else if (c < 768) v = w2_l1_W[k * 256 + (c - 512)];
            else if (c < 778) v = w01_W[k * 10 + (c - 768)];
            else if (c == 778) v = b01_W[k];
            else if (c == 779) v = b00_W[k];
            else if (c < 812) v = b1_W[k * 32 + (c - 780)];
            else              v = b2_l1_W[k * 32 + (c - 812)];
        }
        g_BT[idx] = __float2half(v);
    }
    if (idx < NCATP) {
        int c = idx;
        float v = 0.f;
        if (c < NCAT) {
            if      (c < 256) v = w00_l1_b[c];
            else if (c < 512) v = w1_l1_b[c - 256];
            else if (c < 768) v = w2_l1_b[c - 512];
            else if (c < 778) v = w01_b[c - 768];
            else if (c == 778) v = b01_b[0];
            else if (c == 779) v = b00_b[0];
            else if (c < 812) v = b1_b[c - 780];
            else              v = b2_l1_b[c - 812];
        }
        g_biascat[c] = v;
    }
    // fused "all-ones onehot row" deltas
    if (idx < Hh) {
        float s = 0.f;
        #pragma unroll
        for (int j = 0; j < NVv; j++) s += w00_l1_W[(SDd + j) * 256 + idx];
        g_hdelta[idx] = s;
    }
    if (idx == Hh) {
        float s = 0.f;
        #pragma unroll
        for (int j = 0; j < NVv; j++) s += b00_W[SDd + j];
        g_gdelta[0] = s;
    }
}

// Block-diagonal B for GEMM2: rows(k) 0-255 -> w1_l2 (cols 0-543),
// rows 256-511 -> w2_l2 (cols 544-575). Zero elsewhere.
__global__ void pack2_kernel(const float* __restrict__ w1_l2_W, const float* __restrict__ w1_l2_b,
                             const float* __restrict__ w2_l2_W, const float* __restrict__ w2_l2_b)
{
    int idx = blockIdx.x * blockDim.x + threadIdx.x;   // over N2P*K2
    if (idx < N2P * K2) {
        int c = idx / K2;
        int k = idx - c * K2;
        float v = 0.f;
        if (c < N2) { if (k < 256) v = w1_l2_W[k * N2 + c]; }
        else        { if (k >= 256) v = w2_l2_W[(k - 256) * Ee + (c - N2)]; }
        g_B2T[idx] = __float2half(v);
    }
    if (idx < N2P) g_bias2[idx] = (idx < N2) ? w1_l2_b[idx] : w2_l2_b[idx - N2];
}

// ---------------------------------------------------------------------------
// mma.sync fp16 GEMM (single term), 2-stage cp.async pipeline.
// Per-tile K range: tiles with bn+64 <= split_col use Ksmall, else Kfull
// (supports the block-diagonal GEMM2 without paying full K on dense tiles).
// WRITE_MID: cols [256,768) -> relu + fp16 to g_MID (fp32 store skipped).
// ---------------------------------------------------------------------------
#define SROW    144
#define OF_A    0
#define OF_B    (128 * SROW)            // 18432
#define STAGE   (OF_B + 64 * SROW)      // 27648
#define SMTOT   (2 * STAGE)             // 55296

template <bool WRITE_MID>
__global__ void __launch_bounds__(256)
gemm_mma(const __half* __restrict__ A, int lda,
         const __half* __restrict__ B, int ldb,
         const float* __restrict__ bias,
         float* __restrict__ C, int ldc, int Nvalid,
         int Kfull, int Ksmall, int split_col)
{
    extern __shared__ char smem[];
    const uint32_t sb = smem_u32(smem);
    const int tid  = threadIdx.x;
    const int w    = tid >> 5;
    const int lane = tid & 31;
    const int wm   = w & 3;
    const int wn   = w >> 2;
    const int bm   = blockIdx.y * 128;
    const int bn   = blockIdx.x * 64;

    const int K = (bn + 64 <= split_col) ? Ksmall : Kfull;

    float acc[2][4][4];
    #pragma unroll
    for (int mt = 0; mt < 2; mt++)
        #pragma unroll
        for (int nt = 0; nt < 4; nt++)
            #pragma unroll
            for (int i = 0; i < 4; i++) acc[mt][nt][i] = 0.f;

    const int nch = K >> 6;
    const int arow = tid >> 3, asec = tid & 7;

    #define ISSUE_LOADS(c_, s_) do {                                             \
        const int k0_ = (c_) << 6;                                               \
        const uint32_t base_ = sb + (s_) * STAGE;                                \
        _Pragma("unroll")                                                        \
        for (int i = 0; i < 4; i++) {                                            \
            int row_ = arow + i * 32;                                            \
            uint32_t so_ = base_ + row_ * SROW + asec * 16;                      \
            const size_t go_ = (size_t)(bm + row_) * lda + k0_ + asec * 8;       \
            CP_ASYNC16(so_ + OF_A, (const char*)(A + go_));                      \
        }                                                                        \
        _Pragma("unroll")                                                        \
        for (int i = 0; i < 2; i++) {                                            \
            int row_ = arow + i * 32;                                            \
            uint32_t so_ = base_ + row_ * SROW + asec * 16;                      \
            const size_t go_ = (size_t)(bn + row_) * ldb + k0_ + asec * 8;       \
            CP_ASYNC16(so_ + OF_B, (const char*)(B + go_));                      \
        }                                                                        \
        CP_COMMIT();                                                             \
    } while (0)

    ISSUE_LOADS(0, 0);

    for (int c = 0; c < nch; c++) {
        if (c + 1 < nch) { ISSUE_LOADS(c + 1, (c + 1) & 1); CP_WAIT(1); }
        else             { CP_WAIT(0); }
        __syncthreads();

        const uint32_t stb = sb + (c & 1) * STAGE;
        #pragma unroll
        for (int ks = 0; ks < 4; ks++) {
            uint32_t ah[2][4];
            #pragma unroll
            for (int mt = 0; mt < 2; mt++) {
                int ar = wm * 32 + mt * 16 + (lane & 15);
                int ak = ks * 16 + (lane >> 4) * 8;
                ldsm_x4(ah[mt], stb + OF_A + (uint32_t)(ar * SROW + ak * 2));
            }
            uint32_t bh[4][2];
            #pragma unroll
            for (int jp = 0; jp < 2; jp++) {
                int tilei = lane >> 3, rin = lane & 7;
                int nrow = wn * 32 + jp * 16 + (tilei >> 1) * 8 + rin;
                int kof  = ks * 16 + (tilei & 1) * 8;
                uint32_t r[4];
                ldsm_x4(r, stb + OF_B + (uint32_t)(nrow * SROW + kof * 2));
                bh[jp*2][0] = r[0]; bh[jp*2][1] = r[1];
                bh[jp*2+1][0] = r[2]; bh[jp*2+1][1] = r[3];
            }
            #pragma unroll
            for (int mt = 0; mt < 2; mt++)
                #pragma unroll
                for (int nt = 0; nt < 4; nt++)
                    mma_f16(acc[mt][nt], ah[mt], bh[nt]);
        }
        __syncthreads();
    }

    // Epilogue
    const int trow  = lane >> 2;
    const int tcol2 = (lane & 3) * 2;
    #pragma unroll
    for (int mt = 0; mt < 2; mt++) {
        #pragma unroll
        for (int nt = 0; nt < 4; nt++) {
            int col = bn + wn * 32 + nt * 8 + tcol2;
            float bv0 = bias[col], bv1 = bias[col + 1];
            #pragma unroll
            for (int half = 0; half < 2; half++) {
                int row = bm + wm * 32 + mt * 16 + trow + half * 8;
                float v0 = acc[mt][nt][half * 2 + 0] + bv0;
                float v1 = acc[mt][nt][half * 2 + 1] + bv1;
                bool is_mid = WRITE_MID && col >= 256 && col < 768;
                if (is_mid) {
                    float r0 = fmaxf(v0, 0.f), r1 = fmaxf(v1, 0.f);
                    __half h0 = __float2half(r0), h1 = __float2half(r1);
                    uint32_t ph = (uint32_t)__half_as_ushort(h0) | ((uint32_t)__half_as_ushort(h1) << 16);
                    ((uint32_t*)g_MID)[((size_t)row * MIDW + (col - 256)) >> 1] = ph;
                } else if (col < Nvalid) {
                    *(float2*)(C + (size_t)row * ldc + col) = make_float2(v0, v1);
                }
            }
        }
    }
}

// ---------------------------------------------------------------------------
// Final fused kernel: one warp per row (lightweight now; w2 comes from GEMM2).
// ---------------------------------------------------------------------------
__global__ void __launch_bounds__(256)
final_kernel(const float* __restrict__ qvals,
             const int*   __restrict__ cr,
             const float* __restrict__ w00_l2_W,  // (256,4)
             const float* __restrict__ w00_l2_b,  // (4)
             const float* __restrict__ b2_l2_W,   // (32,1)
             const float* __restrict__ b2_l2_b,   // (1)
             float* __restrict__ out)
{
    __shared__ float s_q[8][NAa];

    const int w = threadIdx.x >> 5;
    const int l = threadIdx.x & 31;
    const int r = blockIdx.x * 8 + w;
    const int b = r >> 6;                 // batch index (T = 64)
    const float* __restrict__ row = g_H1 + (size_t)r * NCAT;

    if (l < NAa) s_q[w][l] = qvals[r * NAa + l];
    __syncwarp();

    const bool mod = (b < NVv);

    // --- w00_l2: common + modified (reads H1 cols [0,256) from global, coalesced)
    float acc0[4] = {0.f, 0.f, 0.f, 0.f};
    float accm[4] = {0.f, 0.f, 0.f, 0.f};
    for (int kk = l; kk < Hh; kk += 32) {
        float hb = row[kk];
        float h  = fmaxf(hb, 0.f);
        float hm = fmaxf(hb + g_hdelta[kk], 0.f);
        float4 wv = *(const float4*)(w00_l2_W + kk * 4);
        acc0[0] += h  * wv.x; acc0[1] += h  * wv.y; acc0[2] += h  * wv.z; acc0[3] += h  * wv.w;
        accm[0] += hm * wv.x; accm[1] += hm * wv.y; accm[2] += hm * wv.z; accm[3] += hm * wv.w;
    }
    #pragma unroll
    for (int o = 0; o < 4; o++) {
        #pragma unroll
        for (int off = 16; off; off >>= 1) {
            acc0[o] += __shfl_xor_sync(0xffffffffu, acc0[o], off);
            accm[o] += __shfl_xor_sync(0xffffffffu, accm[o], off);
        }
    }
    float w0c[4], w0m[4];
    #pragma unroll
    for (int o = 0; o < 4; o++) {
        w0c[o] = fabsf(acc0[o] + w00_l2_b[o]);
        w0m[o] = fabsf(accm[o] + w00_l2_b[o]);
    }

    // --- w2 from GEMM2 block-diag output (bias already added)
    const float* __restrict__ w1r = g_W1F + (size_t)r * N2P;
    float w2a = fabsf(w1r[N2 + l]);

    // --- b2
    float xb2 = fmaxf(row[812 + l], 0.f) * b2_l2_W[l];
    #pragma unroll
    for (int off = 16; off; off >>= 1) xb2 += __shfl_xor_sync(0xffffffffu, xb2, off);
    float b2 = xb2 + b2_l2_b[0];

    float b1v = row[780 + l];

    // --- group q-values / residual mix
    float gq_l;
    if (l < NVv) {
        const int* __restrict__ crr = cr + (size_t)r * (Kk * NVv);
        float g = 0.f;
        #pragma unroll
        for (int k = 0; k < Kk; k++) {
            int idx = crr[k * NVv + l];
            float wk = (mod && l == b) ? w0m[k] : w0c[k];
            g += s_q[w][idx] * wk;
        }
        g += row[779];
        if (mod && l == b) g += g_gdelta[0];
        gq_l = g;
    } else {
        float oth = row[778];
        #pragma unroll
        for (int a = 0; a < NAa; a++) oth += s_q[w][a] * row[768 + a];
        gq_l = oth;
    }

    // --- hidden = elu(gq @ |w1| + b1)
    float accH = b1v;
    #pragma unroll
    for (int v = 0; v <= NVv; v++) {
        float gqv = __shfl_sync(0xffffffffu, gq_l, v);
        accH += gqv * fabsf(w1r[v * Ee + l]);
    }
    float hidden = (accH > 0.f) ? accH : expm1f(accH);

    float part = hidden * w2a;
    #pragma unroll
    for (int off = 16; off; off >>= 1) part += __shfl_xor_sync(0xffffffffu, part, off);
    if (l == 0) out[r] = part + b2;
}

// ---------------------------------------------------------------------------
extern "C" void kernel_launch(void* const* d_in, const int* in_sizes, int n_in,
                              void* d_out, int out_size)
{
    const float* qvals    = (const float*)d_in[0];
    const int*   cr       = (const int*)  d_in[1];
    const float* states   = (const float*)d_in[2];
    const float* w00_l1_W = (const float*)d_in[3];
    const float* w00_l1_b = (const float*)d_in[4];
    const float* w00_l2_W = (const float*)d_in[5];
    const float* w00_l2_b = (const float*)d_in[6];
    const float* b00_W    = (const float*)d_in[7];
    const float* b00_b    = (const float*)d_in[8];
    const float* w01_W    = (const float*)d_in[9];
    const float* w01_b    = (const float*)d_in[10];
    const float* b01_W    = (const float*)d_in[11];
    const float* b01_b    = (const float*)d_in[12];
    const float* w1_l1_W  = (const float*)d_in[13];
    const float* w1_l1_b  = (const float*)d_in[14];
    const float* w1_l2_W  = (const float*)d_in[15];
    const float* w1_l2_b  = (const float*)d_in[16];
    const float* b1_W     = (const float*)d_in[17];
    const float* b1_b     = (const float*)d_in[18];
    const float* w2_l1_W  = (const float*)d_in[19];
    const float* w2_l1_b  = (const float*)d_in[20];
    const float* w2_l2_W  = (const float*)d_in[21];
    const float* w2_l2_b  = (const float*)d_in[22];
    const float* b2_l1_W  = (const float*)d_in[23];
    const float* b2_l1_b  = (const float*)d_in[24];
    const float* b2_l2_W  = (const float*)d_in[25];
    const float* b2_l2_b  = (const float*)d_in[26];
    float* out = (float*)d_out;

    static int attr_done = 0;
    if (!attr_done) {
        cudaFuncSetAttribute(gemm_mma<true>,  cudaFuncAttributeMaxDynamicSharedMemorySize, SMTOT);
        cudaFuncSetAttribute(gemm_mma<false>, cudaFuncAttributeMaxDynamicSharedMemorySize, SMTOT);
        attr_done = 1;
    }

    float *H1, *W1F, *biascat, *bias2;
    __half *ST, *MID, *BT, *B2T;
    cudaGetSymbolAddress((void**)&H1,      g_H1);
    cudaGetSymbolAddress((void**)&W1F,     g_W1F);
    cudaGetSymbolAddress((void**)&biascat, g_biascat);
    cudaGetSymbolAddress((void**)&bias2,   g_bias2);
    cudaGetSymbolAddress((void**)&ST,      g_ST);
    cudaGetSymbolAddress((void**)&MID,     g_MID);
    cudaGetSymbolAddress((void**)&BT,      g_BT);
    cudaGetSymbolAddress((void**)&B2T,     g_B2T);

    // 1) precompute: fp16 convert + packed weights (+deltas fused)
    split_states<<<(ROWS * SDd / 4 + 255) / 256, 256>>>(states);
    pack1_kernel<<<(NCATP * SDd + 255) / 256, 256>>>(
        w00_l1_W, w00_l1_b, w1_l1_W, w1_l1_b, w2_l1_W, w2_l1_b,
        w01_W, w01_b, b01_W, b01_b, b00_W, b00_b, b1_W, b1_b, b2_l1_W, b2_l1_b);
    pack2_kernel<<<(N2P * K2 + 255) / 256, 256>>>(w1_l2_W, w1_l2_b, w2_l2_W, w2_l2_b);

    // 2) GEMM1: H1 = states @ Bcat + bias; relu+fp16 of cols [256,768) -> MID
    {
        dim3 grid(NCATP / 64, ROWS / 128);
        gemm_mma<true><<<grid, 256, SMTOT>>>(ST, SDd, BT, SDd,
                                             biascat, H1, NCAT, NCAT,
                                             SDd, SDd, 0);
    }

    // 3) GEMM2 (block-diagonal): W1F[:,0:544]=MID[:,0:256]@w1_l2+b,
    //    W1F[:,544:576]=MID[:,256:512]@w2_l2+b. Dense tiles use K=256.
    {
        dim3 grid(N2P / 64, ROWS / 128);
        gemm_mma<false><<<grid, 256, SMTOT>>>(MID, MIDW, B2T, K2,
                                              bias2, W1F, N2P, N2P,
                                              K2, 256, N2);
    }

    // 4) fused epilogue
    final_kernel<<<ROWS / 8, 256>>>(qvals, cr,
                                    w00_l2_W, w00_l2_b,
                                    b2_l2_W, b2_l2_b,
                                    out);
}

// round 14
// speedup vs baseline: 4.4613x; 1.0779x over previous
#include <cuda_runtime.h>
#include <cuda_fp16.h>
#include <math.h>
#include <stdint.h>

// Problem dims
#define Bdim 128
#define Tdim 64
#define NAa  10
#define NVv  16
#define Kk   4
#define SDd  512
#define Hh   256
#define Ee   32
#define ROWS (Bdim * Tdim)        // 8192
#define NCAT 844                  // real concat width
#define NCATP 896                 // padded to 14*64
#define N2   544                  // (NV+1)*E
#define N2P  576                  // padded: 544 w1 cols + 32 w2 cols
#define MIDW 512                  // MID width: relu(H1[:,256:768])
#define K2   512                  // GEMM2 full K (block-diagonal)

// ---------------- scratch (__device__ globals; no cudaMalloc) ----------------
__device__ float g_H1[(size_t)ROWS * NCAT];           // GEMM1 out (fp32; mid cols skipped)
__device__ float g_W1F[(size_t)ROWS * N2P];           // GEMM2 out (fp32)
__device__ __align__(16) __half g_ST [(size_t)ROWS * SDd];    // states fp16
__device__ __align__(16) __half g_MID[(size_t)ROWS * MIDW];   // relu(H1[:,256:768]) fp16
__device__ __align__(16) __half g_BT [(size_t)NCATP * SDd];   // B^T GEMM1 [c][k]
__device__ __align__(16) __half g_B2T[(size_t)N2P * K2];      // B^T GEMM2 block-diagonal
__device__ float g_biascat[NCATP];
__device__ float g_bias2[N2P];
__device__ float g_hdelta[Hh];
__device__ float g_gdelta[1];

// ---------------- helpers ----------------
__device__ __forceinline__ uint32_t smem_u32(const void* p) {
    uint32_t a;
    asm("{ .reg .u64 t; cvta.to.shared.u64 t, %1; cvt.u32.u64 %0, t; }" : "=r"(a) : "l"(p));
    return a;
}
__device__ __forceinline__ void ldsm_x4(uint32_t* r, uint32_t addr) {
    asm volatile("ldmatrix.sync.aligned.m8n8.x4.shared.b16 {%0,%1,%2,%3}, [%4];"
                 : "=r"(r[0]), "=r"(r[1]), "=r"(r[2]), "=r"(r[3]) : "r"(addr));
}
__device__ __forceinline__ void mma_f16(float* c, const uint32_t* a, const uint32_t* b) {
    asm volatile("mma.sync.aligned.m16n8k16.row.col.f32.f16.f16.f32 "
                 "{%0,%1,%2,%3}, {%4,%5,%6,%7}, {%8,%9}, {%0,%1,%2,%3};"
                 : "+f"(c[0]), "+f"(c[1]), "+f"(c[2]), "+f"(c[3])
                 : "r"(a[0]), "r"(a[1]), "r"(a[2]), "r"(a[3]), "r"(b[0]), "r"(b[1]));
}
#define CP_ASYNC16(dst, src) \
    asm volatile("cp.async.cg.shared.global [%0], [%1], 16;" :: "r"(dst), "l"(src))
#define CP_COMMIT() asm volatile("cp.async.commit_group;" ::: "memory")
#define CP_WAIT(n)  asm volatile("cp.async.wait_group %0;" :: "n"(n) : "memory")

// ---------------- merged prep kernel ----------------
#define N_SPLIT (ROWS * SDd / 4)      // 1048576
#define N_P1    (NCATP * SDd)         // 458752
#define N_P2    (N2P * K2)            // 294912
#define N_PREP  (N_SPLIT + N_P1 + N_P2)

__global__ void prep_kernel(
    const float* __restrict__ states,
    const float* __restrict__ w00_l1_W, const float* __restrict__ w00_l1_b,
    const float* __restrict__ w1_l1_W,  const float* __restrict__ w1_l1_b,
    const float* __restrict__ w2_l1_W,  const float* __restrict__ w2_l1_b,
    const float* __restrict__ w01_W,    const float* __restrict__ w01_b,
    const float* __restrict__ b01_W,    const float* __restrict__ b01_b,
    const float* __restrict__ b00_W,    const float* __restrict__ b00_b,
    const float* __restrict__ b1_W,     const float* __restrict__ b1_b,
    const float* __restrict__ b2_l1_W,  const float* __restrict__ b2_l1_b,
    const float* __restrict__ w1_l2_W,  const float* __restrict__ w1_l2_b,
    const float* __restrict__ w2_l2_W,  const float* __restrict__ w2_l2_b)
{
    int gidx = blockIdx.x * blockDim.x + threadIdx.x;

    if (gidx < N_SPLIT) {
        // states -> fp16
        float4 v = ((const float4*)states)[gidx];
        __half h0 = __float2half(v.x), h1 = __float2half(v.y);
        __half h2 = __float2half(v.z), h3 = __float2half(v.w);
        uint32_t hA = (uint32_t)__half_as_ushort(h0) | ((uint32_t)__half_as_ushort(h1) << 16);
        uint32_t hB = (uint32_t)__half_as_ushort(h2) | ((uint32_t)__half_as_ushort(h3) << 16);
        ((uint2*)g_ST)[gidx] = make_uint2(hA, hB);
        return;
    }
    int idx = gidx - N_SPLIT;
    if (idx < N_P1) {
        int c = idx / SDd;
        int k = idx - c * SDd;
        float v = 0.f;
        if (c < NCAT) {
            if      (c < 256) v = w00_l1_W[k * 256 + c];
            else if (c < 512) v = w1_l1_W[k * 256 + (c - 256)];
            else if (c < 768) v = w2_l1_W[k * 256 + (c - 512)];
            else if (c < 778) v = w01_W[k * 10 + (c - 768)];
            else if (c == 778) v = b01_W[k];
            else if (c == 779) v = b00_W[k];
            else if (c < 812) v = b1_W[k * 32 + (c - 780)];
            else              v = b2_l1_W[k * 32 + (c - 812)];
        }
        g_BT[idx] = __float2half(v);

        if (idx < NCATP) {
            int cc = idx;
            float bv = 0.f;
            if (cc < NCAT) {
                if      (cc < 256) bv = w00_l1_b[cc];
                else if (cc < 512) bv = w1_l1_b[cc - 256];
                else if (cc < 768) bv = w2_l1_b[cc - 512];
                else if (cc < 778) bv = w01_b[cc - 768];
                else if (cc == 778) bv = b01_b[0];
                else if (cc == 779) bv = b00_b[0];
                else if (cc < 812) bv = b1_b[cc - 780];
                else               bv = b2_l1_b[cc - 812];
            }
            g_biascat[cc] = bv;
        }
        if (idx < Hh) {
            float s = 0.f;
            #pragma unroll
            for (int j = 0; j < NVv; j++) s += w00_l1_W[(SDd + j) * 256 + idx];
            g_hdelta[idx] = s;
        }
        if (idx == Hh) {
            float s = 0.f;
            #pragma unroll
            for (int j = 0; j < NVv; j++) s += b00_W[SDd + j];
            g_gdelta[0] = s;
        }
        return;
    }
    idx -= N_P1;
    if (idx < N_P2) {
        int c = idx / K2;
        int k = idx - c * K2;
        float v = 0.f;
        if (c < N2) { if (k < 256) v = w1_l2_W[k * N2 + c]; }
        else        { if (k >= 256) v = w2_l2_W[(k - 256) * Ee + (c - N2)]; }
        g_B2T[idx] = __float2half(v);
        if (idx < N2P) g_bias2[idx] = (idx < N2) ? w1_l2_b[idx] : w2_l2_b[idx - N2];
    }
}

// ---------------------------------------------------------------------------
// mma.sync fp16 GEMM, 2-stage cp.async smem pipeline + double-buffered
// register fragments in the ks loop.
// Per-tile K range: tiles with bn+64 <= split_col use Ksmall, else Kfull.
// WRITE_MID: cols [256,768) -> relu + fp16 to g_MID (fp32 store skipped).
// ---------------------------------------------------------------------------
#define SROW    144
#define OF_A    0
#define OF_B    (128 * SROW)            // 18432
#define STAGE   (OF_B + 64 * SROW)      // 27648
#define SMTOT   (2 * STAGE)             // 55296

__device__ __forceinline__ void load_a_frags(uint32_t stb, int ks, uint32_t a[2][4],
                                             int wm, int lane) {
    #pragma unroll
    for (int mt = 0; mt < 2; mt++) {
        int ar = wm * 32 + mt * 16 + (lane & 15);
        int ak = ks * 16 + (lane >> 4) * 8;
        ldsm_x4(a[mt], stb + OF_A + (uint32_t)(ar * SROW + ak * 2));
    }
}
__device__ __forceinline__ void load_b_frags(uint32_t stb, int ks, uint32_t b[4][2],
                                             int wn, int lane) {
    #pragma unroll
    for (int jp = 0; jp < 2; jp++) {
        int tilei = lane >> 3, rin = lane & 7;
        int nrow = wn * 32 + jp * 16 + (tilei >> 1) * 8 + rin;
        int kof  = ks * 16 + (tilei & 1) * 8;
        uint32_t r[4];
        ldsm_x4(r, stb + OF_B + (uint32_t)(nrow * SROW + kof * 2));
        b[jp*2][0] = r[0]; b[jp*2][1] = r[1];
        b[jp*2+1][0] = r[2]; b[jp*2+1][1] = r[3];
    }
}

template <bool WRITE_MID>
__global__ void __launch_bounds__(256)
gemm_mma(const __half* __restrict__ A, int lda,
         const __half* __restrict__ B, int ldb,
         const float* __restrict__ bias,
         float* __restrict__ C, int ldc, int Nvalid,
         int Kfull, int Ksmall, int split_col)
{
    extern __shared__ char smem[];
    const uint32_t sb = smem_u32(smem);
    const int tid  = threadIdx.x;
    const int w    = tid >> 5;
    const int lane = tid & 31;
    const int wm   = w & 3;
    const int wn   = w >> 2;
    const int bm   = blockIdx.y * 128;
    const int bn   = blockIdx.x * 64;

    const int K = (bn + 64 <= split_col) ? Ksmall : Kfull;

    float acc[2][4][4];
    #pragma unroll
    for (int mt = 0; mt < 2; mt++)
        #pragma unroll
        for (int nt = 0; nt < 4; nt++)
            #pragma unroll
            for (int i = 0; i < 4; i++) acc[mt][nt][i] = 0.f;

    const int nch = K >> 6;
    const int arow = tid >> 3, asec = tid & 7;

    #define ISSUE_LOADS(c_, s_) do {                                             \
        const int k0_ = (c_) << 6;                                               \
        const uint32_t base_ = sb + (s_) * STAGE;                                \
        _Pragma("unroll")                                                        \
        for (int i = 0; i < 4; i++) {                                            \
            int row_ = arow + i * 32;                                            \
            uint32_t so_ = base_ + row_ * SROW + asec * 16;                      \
            const size_t go_ = (size_t)(bm + row_) * lda + k0_ + asec * 8;       \
            CP_ASYNC16(so_ + OF_A, (const char*)(A + go_));                      \
        }                                                                        \
        _Pragma("unroll")                                                        \
        for (int i = 0; i < 2; i++) {                                            \
            int row_ = arow + i * 32;                                            \
            uint32_t so_ = base_ + row_ * SROW + asec * 16;                      \
            const size_t go_ = (size_t)(bn + row_) * ldb + k0_ + asec * 8;       \
            CP_ASYNC16(so_ + OF_B, (const char*)(B + go_));                      \
        }                                                                        \
        CP_COMMIT();                                                             \
    } while (0)

    ISSUE_LOADS(0, 0);

    for (int c = 0; c < nch; c++) {
        if (c + 1 < nch) { ISSUE_LOADS(c + 1, (c + 1) & 1); CP_WAIT(1); }
        else             { CP_WAIT(0); }
        __syncthreads();

        const uint32_t stb = sb + (c & 1) * STAGE;

        uint32_t ah[2][2][4], bh[2][4][2];
        load_a_frags(stb, 0, ah[0], wm, lane);
        load_b_frags(stb, 0, bh[0], wn, lane);

        #pragma unroll
        for (int ks = 0; ks < 4; ks++) {
            const int cur = ks & 1;
            if (ks < 3) {
                load_a_frags(stb, ks + 1, ah[cur ^ 1], wm, lane);
                load_b_frags(stb, ks + 1, bh[cur ^ 1], wn, lane);
            }
            #pragma unroll
            for (int mt = 0; mt < 2; mt++)
                #pragma unroll
                for (int nt = 0; nt < 4; nt++)
                    mma_f16(acc[mt][nt], ah[cur][mt], bh[cur][nt]);
        }
        __syncthreads();
    }

    // Epilogue
    const int trow  = lane >> 2;
    const int tcol2 = (lane & 3) * 2;
    #pragma unroll
    for (int mt = 0; mt < 2; mt++) {
        #pragma unroll
        for (int nt = 0; nt < 4; nt++) {
            int col = bn + wn * 32 + nt * 8 + tcol2;
            float bv0 = bias[col], bv1 = bias[col + 1];
            #pragma unroll
            for (int half = 0; half < 2; half++) {
                int row = bm + wm * 32 + mt * 16 + trow + half * 8;
                float v0 = acc[mt][nt][half * 2 + 0] + bv0;
                float v1 = acc[mt][nt][half * 2 + 1] + bv1;
                bool is_mid = WRITE_MID && col >= 256 && col < 768;
                if (is_mid) {
                    float r0 = fmaxf(v0, 0.f), r1 = fmaxf(v1, 0.f);
                    __half h0 = __float2half(r0), h1 = __float2half(r1);
                    uint32_t ph = (uint32_t)__half_as_ushort(h0) | ((uint32_t)__half_as_ushort(h1) << 16);
                    ((uint32_t*)g_MID)[((size_t)row * MIDW + (col - 256)) >> 1] = ph;
                } else if (col < Nvalid) {
                    *(float2*)(C + (size_t)row * ldc + col) = make_float2(v0, v1);
                }
            }
        }
    }
}

// ---------------------------------------------------------------------------
// Final fused kernel: one warp per row.
// ---------------------------------------------------------------------------
__global__ void __launch_bounds__(256)
final_kernel(const float* __restrict__ qvals,
             const int*   __restrict__ cr,
             const float* __restrict__ w00_l2_W,  // (256,4)
             const float* __restrict__ w00_l2_b,  // (4)
             const float* __restrict__ b2_l2_W,   // (32,1)
             const float* __restrict__ b2_l2_b,   // (1)
             float* __restrict__ out)
{
    __shared__ float s_q[8][NAa];

    const int w = threadIdx.x >> 5;
    const int l = threadIdx.x & 31;
    const int r = blockIdx.x * 8 + w;
    const int b = r >> 6;                 // batch index (T = 64)
    const float* __restrict__ row = g_H1 + (size_t)r * NCAT;

    if (l < NAa) s_q[w][l] = qvals[r * NAa + l];
    __syncwarp();

    const bool mod = (b < NVv);

    float acc0[4] = {0.f, 0.f, 0.f, 0.f};
    float accm[4] = {0.f, 0.f, 0.f, 0.f};
    for (int kk = l; kk < Hh; kk += 32) {
        float hb = row[kk];
        float h  = fmaxf(hb, 0.f);
        float hm = fmaxf(hb + g_hdelta[kk], 0.f);
        float4 wv = *(const float4*)(w00_l2_W + kk * 4);
        acc0[0] += h  * wv.x; acc0[1] += h  * wv.y; acc0[2] += h  * wv.z; acc0[3] += h  * wv.w;
        accm[0] += hm * wv.x; accm[1] += hm * wv.y; accm[2] += hm * wv.z; accm[3] += hm * wv.w;
    }
    #pragma unroll
    for (int o = 0; o < 4; o++) {
        #pragma unroll
        for (int off = 16; off; off >>= 1) {
            acc0[o] += __shfl_xor_sync(0xffffffffu, acc0[o], off);
            accm[o] += __shfl_xor_sync(0xffffffffu, accm[o], off);
        }
    }
    float w0c[4], w0m[4];
    #pragma unroll
    for (int o = 0; o < 4; o++) {
        w0c[o] = fabsf(acc0[o] + w00_l2_b[o]);
        w0m[o] = fabsf(accm[o] + w00_l2_b[o]);
    }

    const float* __restrict__ w1r = g_W1F + (size_t)r * N2P;
    float w2a = fabsf(w1r[N2 + l]);

    float xb2 = fmaxf(row[812 + l], 0.f) * b2_l2_W[l];
    #pragma unroll
    for (int off = 16; off; off >>= 1) xb2 += __shfl_xor_sync(0xffffffffu, xb2, off);
    float b2 = xb2 + b2_l2_b[0];

    float b1v = row[780 + l];

    float gq_l;
    if (l < NVv) {
        const int* __restrict__ crr = cr + (size_t)r * (Kk * NVv);
        float g = 0.f;
        #pragma unroll
        for (int k = 0; k < Kk; k++) {
            int idx = crr[k * NVv + l];
            float wk = (mod && l == b) ? w0m[k] : w0c[k];
            g += s_q[w][idx] * wk;
        }
        g += row[779];
        if (mod && l == b) g += g_gdelta[0];
        gq_l = g;
    } else {
        float oth = row[778];
        #pragma unroll
        for (int a = 0; a < NAa; a++) oth += s_q[w][a] * row[768 + a];
        gq_l = oth;
    }

    float accH = b1v;
    #pragma unroll
    for (int v = 0; v <= NVv; v++) {
        float gqv = __shfl_sync(0xffffffffu, gq_l, v);
        accH += gqv * fabsf(w1r[v * Ee + l]);
    }
    float hidden = (accH > 0.f) ? accH : expm1f(accH);

    float part = hidden * w2a;
    #pragma unroll
    for (int off = 16; off; off >>= 1) part += __shfl_xor_sync(0xffffffffu, part, off);
    if (l == 0) out[r] = part + b2;
}

// ---------------------------------------------------------------------------
extern "C" void kernel_launch(void* const* d_in, const int* in_sizes, int n_in,
                              void* d_out, int out_size)
{
    const float* qvals    = (const float*)d_in[0];
    const int*   cr       = (const int*)  d_in[1];
    const float* states   = (const float*)d_in[2];
    const float* w00_l1_W = (const float*)d_in[3];
    const float* w00_l1_b = (const float*)d_in[4];
    const float* w00_l2_W = (const float*)d_in[5];
    const float* w00_l2_b = (const float*)d_in[6];
    const float* b00_W    = (const float*)d_in[7];
    const float* b00_b    = (const float*)d_in[8];
    const float* w01_W    = (const float*)d_in[9];
    const float* w01_b    = (const float*)d_in[10];
    const float* b01_W    = (const float*)d_in[11];
    const float* b01_b    = (const float*)d_in[12];
    const float* w1_l1_W  = (const float*)d_in[13];
    const float* w1_l1_b  = (const float*)d_in[14];
    const float* w1_l2_W  = (const float*)d_in[15];
    const float* w1_l2_b  = (const float*)d_in[16];
    const float* b1_W     = (const float*)d_in[17];
    const float* b1_b     = (const float*)d_in[18];
    const float* w2_l1_W  = (const float*)d_in[19];
    const float* w2_l1_b  = (const float*)d_in[20];
    const float* w2_l2_W  = (const float*)d_in[21];
    const float* w2_l2_b  = (const float*)d_in[22];
    const float* b2_l1_W  = (const float*)d_in[23];
    const float* b2_l1_b  = (const float*)d_in[24];
    const float* b2_l2_W  = (const float*)d_in[25];
    const float* b2_l2_b  = (const float*)d_in[26];
    float* out = (float*)d_out;

    static int attr_done = 0;
    if (!attr_done) {
        cudaFuncSetAttribute(gemm_mma<true>,  cudaFuncAttributeMaxDynamicSharedMemorySize, SMTOT);
        cudaFuncSetAttribute(gemm_mma<false>, cudaFuncAttributeMaxDynamicSharedMemorySize, SMTOT);
        attr_done = 1;
    }

    float *H1, *W1F, *biascat, *bias2;
    __half *ST, *MID, *BT, *B2T;
    cudaGetSymbolAddress((void**)&H1,      g_H1);
    cudaGetSymbolAddress((void**)&W1F,     g_W1F);
    cudaGetSymbolAddress((void**)&biascat, g_biascat);
    cudaGetSymbolAddress((void**)&bias2,   g_bias2);
    cudaGetSymbolAddress((void**)&ST,      g_ST);
    cudaGetSymbolAddress((void**)&MID,     g_MID);
    cudaGetSymbolAddress((void**)&BT,      g_BT);
    cudaGetSymbolAddress((void**)&B2T,     g_B2T);

    // 1) merged precompute (states->fp16, pack1+deltas, pack2 block-diag)
    prep_kernel<<<(N_PREP + 255) / 256, 256>>>(
        states,
        w00_l1_W, w00_l1_b, w1_l1_W, w1_l1_b, w2_l1_W, w2_l1_b,
        w01_W, w01_b, b01_W, b01_b, b00_W, b00_b, b1_W, b1_b, b2_l1_W, b2_l1_b,
        w1_l2_W, w1_l2_b, w2_l2_W, w2_l2_b);

    // 2) GEMM1: H1 = states @ Bcat + bias; relu+fp16 of cols [256,768) -> MID
    {
        dim3 grid(NCATP / 64, ROWS / 128);
        gemm_mma<true><<<grid, 256, SMTOT>>>(ST, SDd, BT, SDd,
                                             biascat, H1, NCAT, NCAT,
                                             SDd, SDd, 0);
    }

    // 3) GEMM2 (block-diagonal)
    {
        dim3 grid(N2P / 64, ROWS / 128);
        gemm_mma<false><<<grid, 256, SMTOT>>>(MID, MIDW, B2T, K2,
                                              bias2, W1F, N2P, N2P,
                                              K2, 256, N2);
    }

    // 4) fused epilogue
    final_kernel<<<ROWS / 8, 256>>>(qvals, cr,
                                    w00_l2_W, w00_l2_b,
                                    b2_l2_W, b2_l2_b,
                                    out);
}